// round 11
// baseline (speedup 1.0000x reference)
#include <cuda_runtime.h>
#include <cuda_bf16.h>
#include <math.h>

#define T_SEQ 2048
#define HID   4096
#define HQ    32
#define HKV   8
#define DH    128
#define GROUPS (HQ / HKV)
#define QKV_N 6144                      // 4096 q | 1024 k | 1024 v
#define K_OFF 4096
#define V_OFF 5120

// q pre-scale: 1/sqrt(128) * log2(e)  (softmax runs in exp2 domain)
#define QSCALE_F ((float)(0.08838834764831845 * 1.4426950408889634))

// ---------------- device scratch (no allocs allowed) ----------------
__device__ float g_qkv[T_SEQ * QKV_N];      // 50 MB  fused q|k|v
__device__ float g_attn[T_SEQ * HQ * DH];   // 32 MB (tf32-rounded)
__device__ float g_Hr [T_SEQ * HID];        // 32 MB  tf32-rounded H
__device__ float g_Wr [HID * QKV_N];        // 100 MB tf32-rounded [Wq|Wk|Wv]
__device__ float g_Wor[HQ * DH * HID];      // 64 MB  tf32-rounded Wo

__device__ __forceinline__ unsigned tf32_cvt(float x) {
    unsigned r;
    asm("cvt.rna.tf32.f32 %0, %1;" : "=r"(r) : "f"(x));
    return r;
}
__device__ __forceinline__ float tf32f(float x) { return __uint_as_float(tf32_cvt(x)); }

__device__ __forceinline__ void mma_tf32(float* d, const unsigned* a, const unsigned* b) {
    asm volatile(
        "mma.sync.aligned.m16n8k8.row.col.f32.tf32.tf32.f32 "
        "{%0,%1,%2,%3}, {%4,%5,%6,%7}, {%8,%9}, {%0,%1,%2,%3};"
        : "+f"(d[0]), "+f"(d[1]), "+f"(d[2]), "+f"(d[3])
        : "r"(a[0]), "r"(a[1]), "r"(a[2]), "r"(a[3]), "r"(b[0]), "r"(b[1]));
}

// ldmatrix x4 (32-bit elements on .b16 layout)
__device__ __forceinline__ void ldsm_x4(unsigned* r, unsigned a) {
    asm volatile("ldmatrix.sync.aligned.m8n8.x4.shared.b16 {%0,%1,%2,%3}, [%4];"
                 : "=r"(r[0]), "=r"(r[1]), "=r"(r[2]), "=r"(r[3]) : "r"(a));
}

__device__ __forceinline__ void cp_async16(void* smem_dst, const void* gmem_src) {
    unsigned s = (unsigned)__cvta_generic_to_shared(smem_dst);
    asm volatile("cp.async.cg.shared.global [%0], [%1], 16;" :: "r"(s), "l"(gmem_src));
}

// MUFU exp2 (force fast path)
__device__ __forceinline__ float ex2_mufu(float x) {
    float y;
    asm("ex2.approx.ftz.f32 %0, %1;" : "=f"(y) : "f"(x));
    return y;
}

// ---------------- packed f32x2 exp2 (FFMA2 pipe) ----------------
struct ExpC {
    unsigned long long magic, nmagic, none, c6, c5, c4, c3, c2, c1, c0;
};
__device__ __forceinline__ unsigned long long pk2(float a) {
    unsigned long long r;
    asm("mov.b64 %0, {%1, %1};" : "=l"(r) : "f"(a));
    return r;
}
__device__ __forceinline__ ExpC make_expc() {
    ExpC C;
    C.magic  = pk2(12582912.f);                 // 1.5 * 2^23
    C.nmagic = pk2(-12582912.f);
    C.none   = pk2(-1.f);
    C.c6 = pk2(1.535336188319500e-4f);
    C.c5 = pk2(1.339887440266574e-3f);
    C.c4 = pk2(9.618437357674640e-3f);
    C.c3 = pk2(5.550332471162809e-2f);
    C.c2 = pk2(2.402264791363012e-1f);
    C.c1 = pk2(6.931472028550421e-1f);
    C.c0 = pk2(1.0f);
    return C;
}
// two exp2's per call on the FMA pipe via fma.rn.f32x2
__device__ __forceinline__ void exp2_pair(float x0, float x1, float& r0, float& r1,
                                          const ExpC& C) {
    x0 = fmaxf(x0, -120.f);
    x1 = fmaxf(x1, -120.f);
    unsigned long long X, T, I, F, P, S, R;
    asm("mov.b64 %0, {%1, %2};" : "=l"(X) : "f"(x0), "f"(x1));
    asm("add.rn.f32x2 %0, %1, %2;" : "=l"(T) : "l"(X), "l"(C.magic));   // t = x + magic
    asm("add.rn.f32x2 %0, %1, %2;" : "=l"(I) : "l"(T), "l"(C.nmagic));  // i = t - magic
    asm("fma.rn.f32x2 %0, %1, %2, %3;" : "=l"(F) : "l"(I), "l"(C.none), "l"(X)); // f = x - i
    asm("fma.rn.f32x2 %0, %1, %2, %3;" : "=l"(P) : "l"(C.c6), "l"(F), "l"(C.c5));
    asm("fma.rn.f32x2 %0, %1, %2, %3;" : "=l"(P) : "l"(P), "l"(F), "l"(C.c4));
    asm("fma.rn.f32x2 %0, %1, %2, %3;" : "=l"(P) : "l"(P), "l"(F), "l"(C.c3));
    asm("fma.rn.f32x2 %0, %1, %2, %3;" : "=l"(P) : "l"(P), "l"(F), "l"(C.c2));
    asm("fma.rn.f32x2 %0, %1, %2, %3;" : "=l"(P) : "l"(P), "l"(F), "l"(C.c1));
    asm("fma.rn.f32x2 %0, %1, %2, %3;" : "=l"(P) : "l"(P), "l"(F), "l"(C.c0));
    // 2^i per half from the magic-bits: s = (bits(t) + (127 - 0x4B400000)) << 23
    unsigned t0, t1;
    asm("mov.b64 {%0, %1}, %2;" : "=r"(t0), "=r"(t1) : "l"(T));
    unsigned s0 = (t0 + (0x7Fu - 0x4B400000u)) << 23;
    unsigned s1 = (t1 + (0x7Fu - 0x4B400000u)) << 23;
    asm("mov.b64 %0, {%1, %2};" : "=l"(S) : "r"(s0), "r"(s1));
    asm("mul.rn.f32x2 %0, %1, %2;" : "=l"(R) : "l"(P), "l"(S));
    asm("mov.b64 {%0, %1}, %2;" : "=f"(r0), "=f"(r1) : "l"(R));
}

// ---------------------------------------------------------------------------
// Prep 1: round H and Wo to tf32 (two regions, one launch)
// ---------------------------------------------------------------------------
__global__ void prep_round_HWo(const float4* __restrict__ H, float4* __restrict__ Hr,
                               const float4* __restrict__ Wo, float4* __restrict__ Wor)
{
    const int nH = T_SEQ * HID / 4;
    const int nO = HQ * DH * HID / 4;
    int stride = gridDim.x * blockDim.x;
    for (int i = blockIdx.x * blockDim.x + threadIdx.x; i < nH + nO; i += stride) {
        const float4* s = (i < nH) ? H + i : Wo + (i - nH);
        float4* d       = (i < nH) ? Hr + i : Wor + (i - nH);
        float4 v = *s;
        v.x = tf32f(v.x); v.y = tf32f(v.y); v.z = tf32f(v.z); v.w = tf32f(v.w);
        *d = v;
    }
}

// Prep 2: pack Wq (rounded) into fused weight at col offset 0
__global__ void prep_pack_Wq(const float4* __restrict__ Wq, float4* __restrict__ Wr)
{
    const int n4 = HID * 4096 / 4;
    int stride = gridDim.x * blockDim.x;
    for (int i = blockIdx.x * blockDim.x + threadIdx.x; i < n4; i += stride) {
        int r = i >> 10, c = i & 1023;            // srcW4 = 1024
        float4 v = Wq[i];
        v.x = tf32f(v.x); v.y = tf32f(v.y); v.z = tf32f(v.z); v.w = tf32f(v.w);
        Wr[(size_t)r * (QKV_N / 4) + c] = v;
    }
}

// Prep 3: pack Wk (col 1024) and Wv (col 1280)
__global__ void prep_pack_WkWv(const float4* __restrict__ Wk,
                               const float4* __restrict__ Wv, float4* __restrict__ Wr)
{
    const int n4 = HID * 1024 / 4;                // per matrix
    int stride = gridDim.x * blockDim.x;
    for (int i = blockIdx.x * blockDim.x + threadIdx.x; i < 2 * n4; i += stride) {
        int which = (i >= n4);
        int j = which ? i - n4 : i;
        int r = j >> 8, c = j & 255;              // srcW4 = 256
        float4 v = which ? Wv[j] : Wk[j];
        v.x = tf32f(v.x); v.y = tf32f(v.y); v.z = tf32f(v.z); v.w = tf32f(v.w);
        Wr[(size_t)r * (QKV_N / 4) + (which ? 1280 : 1024) + c] = v;
    }
}

// ---------------------------------------------------------------------------
// TF32 tensor GEMM, 3-stage cp.async pipeline, ldmatrix A-fragments.
// C[M,N] = A[M,K] @ B[K,N]. Tile 128x128x32, 8 warps, warp 64x32. (R8 exact)
// ---------------------------------------------------------------------------
#define GEMM_SMEM_BYTES (3 * (128 * 36 + 32 * 136) * 4)

__global__ __launch_bounds__(256, 2) void tf32gemm3(const float* __restrict__ A,
                                                    const float* __restrict__ B,
                                                    float* __restrict__ C,
                                                    int M, int N, int K)
{
    extern __shared__ float sm[];
    const int tid  = threadIdx.x;
    const int wid  = tid >> 5;
    const int lane = tid & 31;
    const int g    = lane >> 2;
    const int tg   = lane & 3;
    const int wm   = (wid >> 2) * 64;
    const int wn   = (wid & 3) * 32;
    const int bm   = blockIdx.y * 128;
    const int bn   = blockIdx.x * 128;

    const float* Ab = A + (size_t)bm * K;
    const float* Bb = B + bn;

    const unsigned a_lane_off = (((lane & 15) * 36 + (lane >> 4) * 4) << 2);

    float acc[4][4][4];
#pragma unroll
    for (int mt = 0; mt < 4; mt++)
#pragma unroll
        for (int nt = 0; nt < 4; nt++)
#pragma unroll
            for (int i = 0; i < 4; i++) acc[mt][nt][i] = 0.f;

    const int ntiles = K >> 5;

    auto issue = [&](int t) {
        float* As_ = sm + (t % 3) * 8960;
        float* Bs_ = As_ + 4608;
        const int kt = t << 5;
#pragma unroll
        for (int i_ = 0; i_ < 4; i_++) {
            int f4 = tid + i_ * 256;
            int r_ = f4 >> 3, c4_ = (f4 & 7) << 2;
            cp_async16(As_ + r_ * 36 + c4_, Ab + (size_t)r_ * K + kt + c4_);
            int rb_ = f4 >> 5, cb4_ = (f4 & 31) << 2;
            cp_async16(Bs_ + rb_ * 136 + cb4_, Bb + (size_t)(kt + rb_) * N + cb4_);
        }
        asm volatile("cp.async.commit_group;");
    };

    issue(0);
    issue(1);

    for (int t = 0; t < ntiles; t++) {
        if (t == ntiles - 1) asm volatile("cp.async.wait_group 0;");
        else                 asm volatile("cp.async.wait_group 1;");
        __syncthreads();
        if (t + 2 < ntiles) issue(t + 2);

        const float* As_ = sm + (t % 3) * 8960;
        const float* Bs_ = As_ + 4608;
        const unsigned a_base =
            (unsigned)__cvta_generic_to_shared(As_) + a_lane_off;

#pragma unroll
        for (int kk = 0; kk < 32; kk += 8) {
            unsigned af[4][4], bf[4][2];
#pragma unroll
            for (int mt = 0; mt < 4; mt++)
                ldsm_x4(af[mt], a_base + ((((wm + mt * 16) * 36) + kk) << 2));
#pragma unroll
            for (int nt = 0; nt < 4; nt++) {
                int col = wn + nt * 8;
                bf[nt][0] = __float_as_uint(Bs_[(kk + tg) * 136 + col + g]);
                bf[nt][1] = __float_as_uint(Bs_[(kk + tg + 4) * 136 + col + g]);
            }
#pragma unroll
            for (int mt = 0; mt < 4; mt++)
#pragma unroll
                for (int nt = 0; nt < 4; nt++)
                    mma_tf32(acc[mt][nt], af[mt], bf[nt]);
        }
    }

#pragma unroll
    for (int mt = 0; mt < 4; mt++) {
#pragma unroll
        for (int nt = 0; nt < 4; nt++) {
            int row = bm + wm + mt * 16 + g;
            int col = bn + wn + nt * 8 + tg * 2;
            *(float2*)&C[(size_t)row * N + col]       = make_float2(acc[mt][nt][0], acc[mt][nt][1]);
            *(float2*)&C[(size_t)(row + 8) * N + col] = make_float2(acc[mt][nt][2], acc[mt][nt][3]);
        }
    }
}

// ---------------------------------------------------------------------------
// RoPE in-place on fused qkv. Q pre-scaled by 1/sqrt(D)*log2(e). tf32 rounding.
// ---------------------------------------------------------------------------
__global__ void rope_round_kernel(const float* __restrict__ cosp,
                                  const float* __restrict__ sinp)
{
    const int t = blockIdx.x;
    float* rowp = &g_qkv[(size_t)t * QKV_N];
    for (int p = threadIdx.x; p < (HQ + HKV) * 64; p += blockDim.x) {
        int h = p >> 6;
        int d = p & 63;
        float c = cosp[t * DH + d];
        float s = sinp[t * DH + d];
        float* base = (h < HQ) ? rowp + h * DH : rowp + K_OFF + (h - HQ) * DH;
        float sc = (h < HQ) ? QSCALE_F : 1.0f;
        float x1 = base[d];
        float x2 = base[d + 64];
        base[d]      = tf32f((x1 * c - x2 * s) * sc);
        base[d + 64] = tf32f((x2 * c + x1 * s) * sc);
    }
    for (int i = threadIdx.x; i < HKV * DH; i += blockDim.x) {
        float* pv = rowp + V_OFF + i;
        *pv = tf32f(*pv);
    }
}

// ---------------------------------------------------------------------------
// Tensor-core flash attention (64 queries x 1 head, 128 threads, 2 CTAs/SM).
// No-max exp2 softmax; 50% packed-FFMA2 poly / 50% MUFU exp split.
// ---------------------------------------------------------------------------
#define ATT_SMEM_BYTES ((64 * 132 + 64 * 136 + 64 * 68) * 4)

__global__ __launch_bounds__(128, 2) void attn_mma_kernel()
{
    extern __shared__ float smf[];
    float* Ks = smf;                 // [64][132]
    float* Vs = smf + 64 * 132;      // [64][136]
    float* Ps = Vs + 64 * 136;       // [64][68]

    const int h    = blockIdx.y;
    const int kvh  = h / GROUPS;
    const int qi   = gridDim.x - 1 - blockIdx.x;   // long CTAs first
    const int q0   = qi * 64;
    const int tid  = threadIdx.x;
    const int w    = tid >> 5;
    const int lane = tid & 31;
    const int g    = lane >> 2;
    const int tg   = lane & 3;
    const int wrow = w * 16;

    const ExpC C = make_expc();

    for (int idx = tid; idx < 64 * 32; idx += 128) {
        int r = idx >> 5, c4 = (idx & 31) << 2;
        *(float4*)&Ks[r * 132 + c4] =
            *(const float4*)&g_qkv[(size_t)(q0 + r) * QKV_N + h * DH + c4];
    }
    __syncthreads();
    unsigned qf[16][4];
#pragma unroll
    for (int kk8 = 0; kk8 < 16; kk8++) {
        qf[kk8][0] = __float_as_uint(Ks[(wrow + g) * 132 + kk8 * 8 + tg]);
        qf[kk8][1] = __float_as_uint(Ks[(wrow + g + 8) * 132 + kk8 * 8 + tg]);
        qf[kk8][2] = __float_as_uint(Ks[(wrow + g) * 132 + kk8 * 8 + tg + 4]);
        qf[kk8][3] = __float_as_uint(Ks[(wrow + g + 8) * 132 + kk8 * 8 + tg + 4]);
    }
    __syncthreads();

    float acc_o[16][4];
#pragma unroll
    for (int nt = 0; nt < 16; nt++)
#pragma unroll
        for (int i = 0; i < 4; i++) acc_o[nt][i] = 0.f;
    float l0 = 0.f, l1 = 0.f;

    for (int k0 = 0; k0 <= q0; k0 += 64) {
        for (int idx = tid; idx < 64 * 32; idx += 128) {
            int r = idx >> 5, c4 = (idx & 31) << 2;
            size_t off = (size_t)(k0 + r) * QKV_N + kvh * DH + c4;
            *(float4*)&Ks[r * 132 + c4] = *(const float4*)&g_qkv[off + K_OFF];
            *(float4*)&Vs[r * 136 + c4] = *(const float4*)&g_qkv[off + V_OFF];
        }
        __syncthreads();

        float acc_s[8][4];
#pragma unroll
        for (int nt = 0; nt < 8; nt++)
#pragma unroll
            for (int i = 0; i < 4; i++) acc_s[nt][i] = 0.f;
#pragma unroll
        for (int kk8 = 0; kk8 < 16; kk8++) {
#pragma unroll
            for (int nt = 0; nt < 8; nt++) {
                unsigned b[2];
                b[0] = __float_as_uint(Ks[(nt * 8 + g) * 132 + kk8 * 8 + tg]);
                b[1] = __float_as_uint(Ks[(nt * 8 + g) * 132 + kk8 * 8 + tg + 4]);
                mma_tf32(acc_s[nt], qf[kk8], b);
            }
        }

        const bool diag = (k0 == q0);
        const int r0 = q0 + wrow + g, r1 = r0 + 8;
#pragma unroll
        for (int nt = 0; nt < 8; nt++) {
            float x0 = acc_s[nt][0] - 32.f;
            float x1 = acc_s[nt][1] - 32.f;
            float x2 = acc_s[nt][2] - 32.f;
            float x3 = acc_s[nt][3] - 32.f;
            if (diag) {
                int col0 = k0 + nt * 8 + tg * 2;
                if (col0     > r0) x0 = -1e30f;
                if (col0 + 1 > r0) x1 = -1e30f;
                if (col0     > r1) x2 = -1e30f;
                if (col0 + 1 > r1) x3 = -1e30f;
            }
            float p0, p1, p2, p3;
            if (nt < 4) {                      // 50% on FFMA2 (packed f32x2 poly)
                exp2_pair(x0, x1, p0, p1, C);
                exp2_pair(x2, x3, p2, p3, C);
            } else {                           // 50% on MUFU
                p0 = ex2_mufu(x0); p1 = ex2_mufu(x1);
                p2 = ex2_mufu(x2); p3 = ex2_mufu(x3);
            }
            l0 += p0 + p1;
            l1 += p2 + p3;
            *(float2*)&Ps[(wrow + g) * 68 + nt * 8 + tg * 2]     = make_float2(tf32f(p0), tf32f(p1));
            *(float2*)&Ps[(wrow + g + 8) * 68 + nt * 8 + tg * 2] = make_float2(tf32f(p2), tf32f(p3));
        }
        __syncwarp();

#pragma unroll
        for (int kk8 = 0; kk8 < 8; kk8++) {
            unsigned a[4];
            a[0] = __float_as_uint(Ps[(wrow + g) * 68 + kk8 * 8 + tg]);
            a[1] = __float_as_uint(Ps[(wrow + g + 8) * 68 + kk8 * 8 + tg]);
            a[2] = __float_as_uint(Ps[(wrow + g) * 68 + kk8 * 8 + tg + 4]);
            a[3] = __float_as_uint(Ps[(wrow + g + 8) * 68 + kk8 * 8 + tg + 4]);
#pragma unroll
            for (int nt = 0; nt < 16; nt++) {
                unsigned b[2];
                b[0] = __float_as_uint(Vs[(kk8 * 8 + tg) * 136 + nt * 8 + g]);
                b[1] = __float_as_uint(Vs[(kk8 * 8 + tg + 4) * 136 + nt * 8 + g]);
                mma_tf32(acc_o[nt], a, b);
            }
        }
        __syncthreads();
    }

    l0 += __shfl_xor_sync(0xffffffffu, l0, 1);
    l0 += __shfl_xor_sync(0xffffffffu, l0, 2);
    l1 += __shfl_xor_sync(0xffffffffu, l1, 1);
    l1 += __shfl_xor_sync(0xffffffffu, l1, 2);
    const float inv0 = 1.f / l0;
    const float inv1 = 1.f / l1;

    const int row0 = q0 + wrow + g, row1 = row0 + 8;
#pragma unroll
    for (int nt = 0; nt < 16; nt++) {
        int col = h * DH + nt * 8 + tg * 2;
        *(float2*)&g_attn[(size_t)row0 * (HQ * DH) + col] =
            make_float2(tf32f(acc_o[nt][0] * inv0), tf32f(acc_o[nt][1] * inv0));
        *(float2*)&g_attn[(size_t)row1 * (HQ * DH) + col] =
            make_float2(tf32f(acc_o[nt][2] * inv1), tf32f(acc_o[nt][3] * inv1));
    }
}

// ---------------------------------------------------------------------------
// Launch pipeline (7 launches). Inputs:
// 0 H | 1 pos | 2 cos | 3 sin | 4 Wq | 5 Wk | 6 Wv | 7 Wo
// ---------------------------------------------------------------------------
extern "C" void kernel_launch(void* const* d_in, const int* in_sizes, int n_in,
                              void* d_out, int out_size)
{
    const float* H    = (const float*)d_in[0];
    const float* cosp = (const float*)d_in[2];
    const float* sinp = (const float*)d_in[3];
    const float* Wq   = (const float*)d_in[4];
    const float* Wk   = (const float*)d_in[5];
    const float* Wv   = (const float*)d_in[6];
    const float* Wo   = (const float*)d_in[7];
    float* out = (float*)d_out;

    float *qkv, *attn, *Hr, *Wr, *Wor;
    cudaGetSymbolAddress((void**)&qkv,  g_qkv);
    cudaGetSymbolAddress((void**)&attn, g_attn);
    cudaGetSymbolAddress((void**)&Hr,   g_Hr);
    cudaGetSymbolAddress((void**)&Wr,   g_Wr);
    cudaGetSymbolAddress((void**)&Wor,  g_Wor);

    cudaFuncSetAttribute(tf32gemm3, cudaFuncAttributeMaxDynamicSharedMemorySize, GEMM_SMEM_BYTES);
    cudaFuncSetAttribute(attn_mma_kernel, cudaFuncAttributeMaxDynamicSharedMemorySize, ATT_SMEM_BYTES);

    // Prep (3 launches)
    prep_round_HWo<<<1024, 256>>>((const float4*)H, (float4*)Hr,
                                  (const float4*)Wo, (float4*)Wor);
    prep_pack_Wq<<<1024, 256>>>((const float4*)Wq, (float4*)Wr);
    prep_pack_WkWv<<<1024, 256>>>((const float4*)Wk, (const float4*)Wv, (float4*)Wr);

    // Fused QKV projection (launch 4)
    tf32gemm3<<<dim3(QKV_N / 128, T_SEQ / 128), 256, GEMM_SMEM_BYTES>>>(
        Hr, Wr, qkv, T_SEQ, QKV_N, HID);

    // RoPE (launch 5)
    rope_round_kernel<<<T_SEQ, 256>>>(cosp, sinp);

    // Attention (launch 6)
    attn_mma_kernel<<<dim3(T_SEQ / 64, HQ), 128, ATT_SMEM_BYTES>>>();

    // Output projection (launch 7)
    tf32gemm3<<<dim3(HID / 128, T_SEQ / 128), 256, GEMM_SMEM_BYTES>>>(
        attn, Wor, out, T_SEQ, HID, HQ * DH);
}

// round 12
// speedup vs baseline: 1.5292x; 1.5292x over previous
#include <cuda_runtime.h>
#include <cuda_bf16.h>
#include <math.h>

#define T_SEQ 2048
#define HID   4096
#define HQ    32
#define HKV   8
#define DH    128
#define GROUPS (HQ / HKV)
#define QKV_N 6144                      // 4096 q | 1024 k | 1024 v
#define K_OFF 4096
#define V_OFF 5120

// q pre-scale: 1/sqrt(128) * log2(e)  (softmax runs in exp2 domain)
#define QSCALE_F ((float)(0.08838834764831845 * 1.4426950408889634))

// ---------------- device scratch (no allocs allowed) ----------------
__device__ float g_qkv[T_SEQ * QKV_N];      // 50 MB  fused q|k|v
__device__ float g_attn[T_SEQ * HQ * DH];   // 32 MB (tf32-rounded)
__device__ float g_Hr [T_SEQ * HID];        // 32 MB  tf32-rounded H
__device__ float g_Wr [HID * QKV_N];        // 100 MB tf32-rounded [Wq|Wk|Wv]
__device__ float g_Wor[HQ * DH * HID];      // 64 MB  tf32-rounded Wo

__device__ __forceinline__ unsigned tf32_cvt(float x) {
    unsigned r;
    asm("cvt.rna.tf32.f32 %0, %1;" : "=r"(r) : "f"(x));
    return r;
}
__device__ __forceinline__ float tf32f(float x) { return __uint_as_float(tf32_cvt(x)); }

__device__ __forceinline__ void mma_tf32(float* d, const unsigned* a, const unsigned* b) {
    asm volatile(
        "mma.sync.aligned.m16n8k8.row.col.f32.tf32.tf32.f32 "
        "{%0,%1,%2,%3}, {%4,%5,%6,%7}, {%8,%9}, {%0,%1,%2,%3};"
        : "+f"(d[0]), "+f"(d[1]), "+f"(d[2]), "+f"(d[3])
        : "r"(a[0]), "r"(a[1]), "r"(a[2]), "r"(a[3]), "r"(b[0]), "r"(b[1]));
}

// ldmatrix x4 (32-bit elements on .b16 layout): lane L supplies the 16B row
// address of matrix (L>>3); reg m of lane L = 4B at rowstart[m, L>>2] + (L&3)*4.
__device__ __forceinline__ void ldsm_x4(unsigned* r, unsigned a) {
    asm volatile("ldmatrix.sync.aligned.m8n8.x4.shared.b16 {%0,%1,%2,%3}, [%4];"
                 : "=r"(r[0]), "=r"(r[1]), "=r"(r[2]), "=r"(r[3]) : "r"(a));
}

__device__ __forceinline__ void cp_async16(void* smem_dst, const void* gmem_src) {
    unsigned s = (unsigned)__cvta_generic_to_shared(smem_dst);
    asm volatile("cp.async.cg.shared.global [%0], [%1], 16;" :: "r"(s), "l"(gmem_src));
}

// MUFU exp2 (force fast path)
__device__ __forceinline__ float ex2_mufu(float x) {
    float y;
    asm("ex2.approx.ftz.f32 %0, %1;" : "=f"(y) : "f"(x));
    return y;
}

// FMA-pipe exp2: minimax on f in [-0.5, 0.5], ~1e-7 rel err.
__device__ __forceinline__ float exp2_poly(float x) {
    x = fmaxf(x, -120.f);
    float t = x + 12582912.f;
    float i = t - 12582912.f;
    float f = x - i;
    float p = 1.535336188319500e-4f;
    p = fmaf(p, f, 1.339887440266574e-3f);
    p = fmaf(p, f, 9.618437357674640e-3f);
    p = fmaf(p, f, 5.550332471162809e-2f);
    p = fmaf(p, f, 2.402264791363012e-1f);
    p = fmaf(p, f, 6.931472028550421e-1f);
    p = fmaf(p, f, 1.0f);
    int ii = (int)i;
    return p * __int_as_float((ii + 127) << 23);
}

// ---------------------------------------------------------------------------
// Prep 1: round H and Wo to tf32 (two regions, one launch)
// ---------------------------------------------------------------------------
__global__ void prep_round_HWo(const float4* __restrict__ H, float4* __restrict__ Hr,
                               const float4* __restrict__ Wo, float4* __restrict__ Wor)
{
    const int nH = T_SEQ * HID / 4;
    const int nO = HQ * DH * HID / 4;
    int stride = gridDim.x * blockDim.x;
    for (int i = blockIdx.x * blockDim.x + threadIdx.x; i < nH + nO; i += stride) {
        const float4* s = (i < nH) ? H + i : Wo + (i - nH);
        float4* d       = (i < nH) ? Hr + i : Wor + (i - nH);
        float4 v = *s;
        v.x = tf32f(v.x); v.y = tf32f(v.y); v.z = tf32f(v.z); v.w = tf32f(v.w);
        *d = v;
    }
}

// Prep 2: pack Wq (rounded) into fused weight at col offset 0
__global__ void prep_pack_Wq(const float4* __restrict__ Wq, float4* __restrict__ Wr)
{
    const int n4 = HID * 4096 / 4;
    int stride = gridDim.x * blockDim.x;
    for (int i = blockIdx.x * blockDim.x + threadIdx.x; i < n4; i += stride) {
        int r = i >> 10, c = i & 1023;            // srcW4 = 1024
        float4 v = Wq[i];
        v.x = tf32f(v.x); v.y = tf32f(v.y); v.z = tf32f(v.z); v.w = tf32f(v.w);
        Wr[(size_t)r * (QKV_N / 4) + c] = v;
    }
}

// Prep 3: pack Wk (col 1024) and Wv (col 1280)
__global__ void prep_pack_WkWv(const float4* __restrict__ Wk,
                               const float4* __restrict__ Wv, float4* __restrict__ Wr)
{
    const int n4 = HID * 1024 / 4;                // per matrix
    int stride = gridDim.x * blockDim.x;
    for (int i = blockIdx.x * blockDim.x + threadIdx.x; i < 2 * n4; i += stride) {
        int which = (i >= n4);
        int j = which ? i - n4 : i;
        int r = j >> 8, c = j & 255;              // srcW4 = 256
        float4 v = which ? Wv[j] : Wk[j];
        v.x = tf32f(v.x); v.y = tf32f(v.y); v.z = tf32f(v.z); v.w = tf32f(v.w);
        Wr[(size_t)r * (QKV_N / 4) + (which ? 1280 : 1024) + c] = v;
    }
}

// ---------------------------------------------------------------------------
// TF32 tensor GEMM, 3-stage cp.async pipeline, ldmatrix A-fragments.
// C[M,N] = A[M,K] @ B[K,N]. Tile 128x128x32, 8 warps, warp 64x32. (R8 exact)
// ---------------------------------------------------------------------------
#define GEMM_SMEM_BYTES (3 * (128 * 36 + 32 * 136) * 4)

__global__ __launch_bounds__(256, 2) void tf32gemm3(const float* __restrict__ A,
                                                    const float* __restrict__ B,
                                                    float* __restrict__ C,
                                                    int M, int N, int K)
{
    extern __shared__ float sm[];
    const int tid  = threadIdx.x;
    const int wid  = tid >> 5;
    const int lane = tid & 31;
    const int g    = lane >> 2;
    const int tg   = lane & 3;
    const int wm   = (wid >> 2) * 64;
    const int wn   = (wid & 3) * 32;
    const int bm   = blockIdx.y * 128;
    const int bn   = blockIdx.x * 128;

    const float* Ab = A + (size_t)bm * K;
    const float* Bb = B + bn;

    const unsigned a_lane_off = (((lane & 15) * 36 + (lane >> 4) * 4) << 2);

    float acc[4][4][4];
#pragma unroll
    for (int mt = 0; mt < 4; mt++)
#pragma unroll
        for (int nt = 0; nt < 4; nt++)
#pragma unroll
            for (int i = 0; i < 4; i++) acc[mt][nt][i] = 0.f;

    const int ntiles = K >> 5;

    auto issue = [&](int t) {
        float* As_ = sm + (t % 3) * 8960;
        float* Bs_ = As_ + 4608;
        const int kt = t << 5;
#pragma unroll
        for (int i_ = 0; i_ < 4; i_++) {
            int f4 = tid + i_ * 256;
            int r_ = f4 >> 3, c4_ = (f4 & 7) << 2;
            cp_async16(As_ + r_ * 36 + c4_, Ab + (size_t)r_ * K + kt + c4_);
            int rb_ = f4 >> 5, cb4_ = (f4 & 31) << 2;
            cp_async16(Bs_ + rb_ * 136 + cb4_, Bb + (size_t)(kt + rb_) * N + cb4_);
        }
        asm volatile("cp.async.commit_group;");
    };

    issue(0);
    issue(1);

    for (int t = 0; t < ntiles; t++) {
        if (t == ntiles - 1) asm volatile("cp.async.wait_group 0;");
        else                 asm volatile("cp.async.wait_group 1;");
        __syncthreads();
        if (t + 2 < ntiles) issue(t + 2);

        const float* As_ = sm + (t % 3) * 8960;
        const float* Bs_ = As_ + 4608;
        const unsigned a_base =
            (unsigned)__cvta_generic_to_shared(As_) + a_lane_off;

#pragma unroll
        for (int kk = 0; kk < 32; kk += 8) {
            unsigned af[4][4], bf[4][2];
#pragma unroll
            for (int mt = 0; mt < 4; mt++)
                ldsm_x4(af[mt], a_base + ((((wm + mt * 16) * 36) + kk) << 2));
#pragma unroll
            for (int nt = 0; nt < 4; nt++) {
                int col = wn + nt * 8;
                bf[nt][0] = __float_as_uint(Bs_[(kk + tg) * 136 + col + g]);
                bf[nt][1] = __float_as_uint(Bs_[(kk + tg + 4) * 136 + col + g]);
            }
#pragma unroll
            for (int mt = 0; mt < 4; mt++)
#pragma unroll
                for (int nt = 0; nt < 4; nt++)
                    mma_tf32(acc[mt][nt], af[mt], bf[nt]);
        }
    }

#pragma unroll
    for (int mt = 0; mt < 4; mt++) {
#pragma unroll
        for (int nt = 0; nt < 4; nt++) {
            int row = bm + wm + mt * 16 + g;
            int col = bn + wn + nt * 8 + tg * 2;
            *(float2*)&C[(size_t)row * N + col]       = make_float2(acc[mt][nt][0], acc[mt][nt][1]);
            *(float2*)&C[(size_t)(row + 8) * N + col] = make_float2(acc[mt][nt][2], acc[mt][nt][3]);
        }
    }
}

// ---------------------------------------------------------------------------
// RoPE in-place on fused qkv. Q pre-scaled by 1/sqrt(D)*log2(e). tf32 rounding.
// ---------------------------------------------------------------------------
__global__ void rope_round_kernel(const float* __restrict__ cosp,
                                  const float* __restrict__ sinp)
{
    const int t = blockIdx.x;
    float* rowp = &g_qkv[(size_t)t * QKV_N];
    for (int p = threadIdx.x; p < (HQ + HKV) * 64; p += blockDim.x) {
        int h = p >> 6;
        int d = p & 63;
        float c = cosp[t * DH + d];
        float s = sinp[t * DH + d];
        float* base = (h < HQ) ? rowp + h * DH : rowp + K_OFF + (h - HQ) * DH;
        float sc = (h < HQ) ? QSCALE_F : 1.0f;
        float x1 = base[d];
        float x2 = base[d + 64];
        base[d]      = tf32f((x1 * c - x2 * s) * sc);
        base[d + 64] = tf32f((x2 * c + x1 * s) * sc);
    }
    for (int i = threadIdx.x; i < HKV * DH; i += blockDim.x) {
        float* pv = rowp + V_OFF + i;
        *pv = tf32f(*pv);
    }
}

// ---------------------------------------------------------------------------
// Tensor-core flash attention (64 queries x 1 head, 128 threads, 2 CTAs/SM).
// No-max exp2 softmax; 25% poly / 75% MUFU exp split (R8 proven).
// NEW vs R8: Q-frags, S-loop K-frags, and P@V A-frags via ldmatrix.x4
// (same lane mapping proven in the GEMM; strides 132/68 are 16B-aligned and
// bank-conflict-free: 132 mod 32 = 68 mod 32 = 4).
// smem: Ks[64][132] Vs[64][136] Ps[64][68]
// ---------------------------------------------------------------------------
#define ATT_SMEM_BYTES ((64 * 132 + 64 * 136 + 64 * 68) * 4)

__global__ __launch_bounds__(128, 2) void attn_mma_kernel()
{
    extern __shared__ float smf[];
    float* Ks = smf;                 // [64][132]
    float* Vs = smf + 64 * 132;      // [64][136]
    float* Ps = Vs + 64 * 136;       // [64][68]

    const int h    = blockIdx.y;
    const int kvh  = h / GROUPS;
    const int qi   = gridDim.x - 1 - blockIdx.x;   // long CTAs first
    const int q0   = qi * 64;
    const int tid  = threadIdx.x;
    const int w    = tid >> 5;
    const int lane = tid & 31;
    const int g    = lane >> 2;
    const int tg   = lane & 3;
    const int wrow = w * 16;

    // ldmatrix lane offsets (A-frag pattern: row L&15, 4B-elem L>>4)
    const unsigned k_lane_off = (((lane & 15) * 132 + (lane >> 4) * 4) << 2);
    const unsigned p_lane_off = (((lane & 15) * 68  + (lane >> 4) * 4) << 2);
    const unsigned ks_smem = (unsigned)__cvta_generic_to_shared(Ks);
    const unsigned ps_base = (unsigned)__cvta_generic_to_shared(Ps) + p_lane_off
                             + ((wrow * 68) << 2);

    // stage Q tile into Ks, move to register fragments via ldmatrix
    for (int idx = tid; idx < 64 * 32; idx += 128) {
        int r = idx >> 5, c4 = (idx & 31) << 2;
        *(float4*)&Ks[r * 132 + c4] =
            *(const float4*)&g_qkv[(size_t)(q0 + r) * QKV_N + h * DH + c4];
    }
    __syncthreads();
    unsigned qf[16][4];
    {
        const unsigned q_base = ks_smem + k_lane_off + ((wrow * 132) << 2);
#pragma unroll
        for (int kk8 = 0; kk8 < 16; kk8++)
            ldsm_x4(qf[kk8], q_base + ((kk8 * 8) << 2));
    }
    __syncthreads();

    float acc_o[16][4];
#pragma unroll
    for (int nt = 0; nt < 16; nt++)
#pragma unroll
        for (int i = 0; i < 4; i++) acc_o[nt][i] = 0.f;
    float l0 = 0.f, l1 = 0.f;

    for (int k0 = 0; k0 <= q0; k0 += 64) {
        for (int idx = tid; idx < 64 * 32; idx += 128) {
            int r = idx >> 5, c4 = (idx & 31) << 2;
            size_t off = (size_t)(k0 + r) * QKV_N + kvh * DH + c4;
            *(float4*)&Ks[r * 132 + c4] = *(const float4*)&g_qkv[off + K_OFF];
            *(float4*)&Vs[r * 136 + c4] = *(const float4*)&g_qkv[off + V_OFF];
        }
        __syncthreads();

        // ---- S2 = Qscaled @ K^T ; K-frags via ldmatrix (2 nt per x4)
        float acc_s[8][4];
#pragma unroll
        for (int nt = 0; nt < 8; nt++)
#pragma unroll
            for (int i = 0; i < 4; i++) acc_s[nt][i] = 0.f;
        const unsigned kb_base = ks_smem + k_lane_off;
#pragma unroll
        for (int kk8 = 0; kk8 < 16; kk8++) {
#pragma unroll
            for (int ntp = 0; ntp < 4; ntp++) {
                unsigned kq[4];
                ldsm_x4(kq, kb_base + (((ntp * 16 * 132) + kk8 * 8) << 2));
                // kq: m0=rows+0..7 k-lo, m1=rows+8..15 k-lo, m2=+0..7 k-hi, m3=+8..15 k-hi
                unsigned b0[2] = { kq[0], kq[2] };
                unsigned b1[2] = { kq[1], kq[3] };
                mma_tf32(acc_s[2 * ntp],     qf[kk8], b0);
                mma_tf32(acc_s[2 * ntp + 1], qf[kk8], b1);
            }
        }

        // ---- p = 2^(s2 - 32); causal mask on diagonal tile; no max tracking
        const bool diag = (k0 == q0);
        const int r0 = q0 + wrow + g, r1 = r0 + 8;
#pragma unroll
        for (int nt = 0; nt < 8; nt++) {
            float x0 = acc_s[nt][0] - 32.f;
            float x1 = acc_s[nt][1] - 32.f;
            float x2 = acc_s[nt][2] - 32.f;
            float x3 = acc_s[nt][3] - 32.f;
            if (diag) {
                int col0 = k0 + nt * 8 + tg * 2;
                if (col0     > r0) x0 = -1e30f;
                if (col0 + 1 > r0) x1 = -1e30f;
                if (col0     > r1) x2 = -1e30f;
                if (col0 + 1 > r1) x3 = -1e30f;
            }
            float p0, p1, p2, p3;
            if (nt < 2) {                      // 25% on FMA pipe
                p0 = exp2_poly(x0); p1 = exp2_poly(x1);
                p2 = exp2_poly(x2); p3 = exp2_poly(x3);
            } else {                           // 75% on MUFU
                p0 = ex2_mufu(x0); p1 = ex2_mufu(x1);
                p2 = ex2_mufu(x2); p3 = ex2_mufu(x3);
            }
            l0 += p0 + p1;
            l1 += p2 + p3;
            *(float2*)&Ps[(wrow + g) * 68 + nt * 8 + tg * 2]     = make_float2(tf32f(p0), tf32f(p1));
            *(float2*)&Ps[(wrow + g + 8) * 68 + nt * 8 + tg * 2] = make_float2(tf32f(p2), tf32f(p3));
        }
        __syncwarp();   // Ps rows are warp-private

        // ---- O += P @ V ; Ps A-frags via ldmatrix
#pragma unroll
        for (int kk8 = 0; kk8 < 8; kk8++) {
            unsigned a[4];
            ldsm_x4(a, ps_base + ((kk8 * 8) << 2));
#pragma unroll
            for (int nt = 0; nt < 16; nt++) {
                unsigned b[2];
                b[0] = __float_as_uint(Vs[(kk8 * 8 + tg) * 136 + nt * 8 + g]);
                b[1] = __float_as_uint(Vs[(kk8 * 8 + tg + 4) * 136 + nt * 8 + g]);
                mma_tf32(acc_o[nt], a, b);
            }
        }
        __syncthreads();
    }

    l0 += __shfl_xor_sync(0xffffffffu, l0, 1);
    l0 += __shfl_xor_sync(0xffffffffu, l0, 2);
    l1 += __shfl_xor_sync(0xffffffffu, l1, 1);
    l1 += __shfl_xor_sync(0xffffffffu, l1, 2);
    const float inv0 = 1.f / l0;
    const float inv1 = 1.f / l1;

    const int row0 = q0 + wrow + g, row1 = row0 + 8;
#pragma unroll
    for (int nt = 0; nt < 16; nt++) {
        int col = h * DH + nt * 8 + tg * 2;
        *(float2*)&g_attn[(size_t)row0 * (HQ * DH) + col] =
            make_float2(tf32f(acc_o[nt][0] * inv0), tf32f(acc_o[nt][1] * inv0));
        *(float2*)&g_attn[(size_t)row1 * (HQ * DH) + col] =
            make_float2(tf32f(acc_o[nt][2] * inv1), tf32f(acc_o[nt][3] * inv1));
    }
}

// ---------------------------------------------------------------------------
// Launch pipeline (7 launches). Inputs:
// 0 H | 1 pos | 2 cos | 3 sin | 4 Wq | 5 Wk | 6 Wv | 7 Wo
// ---------------------------------------------------------------------------
extern "C" void kernel_launch(void* const* d_in, const int* in_sizes, int n_in,
                              void* d_out, int out_size)
{
    const float* H    = (const float*)d_in[0];
    const float* cosp = (const float*)d_in[2];
    const float* sinp = (const float*)d_in[3];
    const float* Wq   = (const float*)d_in[4];
    const float* Wk   = (const float*)d_in[5];
    const float* Wv   = (const float*)d_in[6];
    const float* Wo   = (const float*)d_in[7];
    float* out = (float*)d_out;

    float *qkv, *attn, *Hr, *Wr, *Wor;
    cudaGetSymbolAddress((void**)&qkv,  g_qkv);
    cudaGetSymbolAddress((void**)&attn, g_attn);
    cudaGetSymbolAddress((void**)&Hr,   g_Hr);
    cudaGetSymbolAddress((void**)&Wr,   g_Wr);
    cudaGetSymbolAddress((void**)&Wor,  g_Wor);

    cudaFuncSetAttribute(tf32gemm3, cudaFuncAttributeMaxDynamicSharedMemorySize, GEMM_SMEM_BYTES);
    cudaFuncSetAttribute(attn_mma_kernel, cudaFuncAttributeMaxDynamicSharedMemorySize, ATT_SMEM_BYTES);

    // Prep (3 launches)
    prep_round_HWo<<<1024, 256>>>((const float4*)H, (float4*)Hr,
                                  (const float4*)Wo, (float4*)Wor);
    prep_pack_Wq<<<1024, 256>>>((const float4*)Wq, (float4*)Wr);
    prep_pack_WkWv<<<1024, 256>>>((const float4*)Wk, (const float4*)Wv, (float4*)Wr);

    // Fused QKV projection (launch 4)
    tf32gemm3<<<dim3(QKV_N / 128, T_SEQ / 128), 256, GEMM_SMEM_BYTES>>>(
        Hr, Wr, qkv, T_SEQ, QKV_N, HID);

    // RoPE (launch 5)
    rope_round_kernel<<<T_SEQ, 256>>>(cosp, sinp);

    // Attention (launch 6)
    attn_mma_kernel<<<dim3(T_SEQ / 64, HQ), 128, ATT_SMEM_BYTES>>>();

    // Output projection (launch 7)
    tf32gemm3<<<dim3(HID / 128, T_SEQ / 128), 256, GEMM_SMEM_BYTES>>>(
        attn, Wor, out, T_SEQ, HID, HQ * DH);
}

// round 13
// speedup vs baseline: 2.1509x; 1.4065x over previous
#include <cuda_runtime.h>
#include <cuda_bf16.h>
#include <cuda_fp16.h>
#include <math.h>

#define T_SEQ 2048
#define HID   4096
#define HQ    32
#define HKV   8
#define DH    128
#define GROUPS (HQ / HKV)
#define QKV_N 6144                      // 4096 q | 1024 k | 1024 v
#define K_OFF 4096
#define V_OFF 5120

// q pre-scale: 1/sqrt(128) * log2(e)  (softmax runs in exp2 domain)
#define QSCALE_F ((float)(0.08838834764831845 * 1.4426950408889634))

// ---------------- device scratch (no allocs allowed) ----------------
__device__ float  g_qkv[T_SEQ * QKV_N];       // 50 MB  fused q|k|v (fp32)
__device__ __half g_attnh[T_SEQ * HQ * DH];   // 16 MB  attention out (fp16)
__device__ __half g_Hh [T_SEQ * HID];         // 16 MB  fp16 H [M][K]
__device__ __half g_Wh [QKV_N * HID];         // 48 MB  fp16 [Wq|Wk|Wv] transposed [N][K]
__device__ __half g_Woh[HID * HQ * DH];       // 32 MB  fp16 Wo transposed [N][K]

__device__ __forceinline__ unsigned tf32_cvt(float x) {
    unsigned r;
    asm("cvt.rna.tf32.f32 %0, %1;" : "=r"(r) : "f"(x));
    return r;
}
__device__ __forceinline__ float tf32f(float x) { return __uint_as_float(tf32_cvt(x)); }

__device__ __forceinline__ void mma_tf32(float* d, const unsigned* a, const unsigned* b) {
    asm volatile(
        "mma.sync.aligned.m16n8k8.row.col.f32.tf32.tf32.f32 "
        "{%0,%1,%2,%3}, {%4,%5,%6,%7}, {%8,%9}, {%0,%1,%2,%3};"
        : "+f"(d[0]), "+f"(d[1]), "+f"(d[2]), "+f"(d[3])
        : "r"(a[0]), "r"(a[1]), "r"(a[2]), "r"(a[3]), "r"(b[0]), "r"(b[1]));
}

__device__ __forceinline__ void mma_f16(float* d, const unsigned* a, const unsigned* b) {
    asm volatile(
        "mma.sync.aligned.m16n8k16.row.col.f32.f16.f16.f32 "
        "{%0,%1,%2,%3}, {%4,%5,%6,%7}, {%8,%9}, {%0,%1,%2,%3};"
        : "+f"(d[0]), "+f"(d[1]), "+f"(d[2]), "+f"(d[3])
        : "r"(a[0]), "r"(a[1]), "r"(a[2]), "r"(a[3]), "r"(b[0]), "r"(b[1]));
}

// ldmatrix x4: lane L supplies the 16B row address of matrix (L>>3).
__device__ __forceinline__ void ldsm_x4(unsigned* r, unsigned a) {
    asm volatile("ldmatrix.sync.aligned.m8n8.x4.shared.b16 {%0,%1,%2,%3}, [%4];"
                 : "=r"(r[0]), "=r"(r[1]), "=r"(r[2]), "=r"(r[3]) : "r"(a));
}

__device__ __forceinline__ void cp_async16(void* smem_dst, const void* gmem_src) {
    unsigned s = (unsigned)__cvta_generic_to_shared(smem_dst);
    asm volatile("cp.async.cg.shared.global [%0], [%1], 16;" :: "r"(s), "l"(gmem_src));
}

// MUFU exp2
__device__ __forceinline__ float ex2_mufu(float x) {
    float y;
    asm("ex2.approx.ftz.f32 %0, %1;" : "=f"(y) : "f"(x));
    return y;
}

// FMA-pipe exp2: minimax on f in [-0.5, 0.5], ~1e-7 rel err.
__device__ __forceinline__ float exp2_poly(float x) {
    x = fmaxf(x, -120.f);
    float t = x + 12582912.f;
    float i = t - 12582912.f;
    float f = x - i;
    float p = 1.535336188319500e-4f;
    p = fmaf(p, f, 1.339887440266574e-3f);
    p = fmaf(p, f, 9.618437357674640e-3f);
    p = fmaf(p, f, 5.550332471162809e-2f);
    p = fmaf(p, f, 2.402264791363012e-1f);
    p = fmaf(p, f, 6.931472028550421e-1f);
    p = fmaf(p, f, 1.0f);
    int ii = (int)i;
    return p * __int_as_float((ii + 127) << 23);
}

// ---------------------------------------------------------------------------
// Prep 1: convert H to fp16 [M][K]
// ---------------------------------------------------------------------------
__global__ void prep_H_half(const float4* __restrict__ H, __half2* __restrict__ Hh)
{
    const int n4 = T_SEQ * HID / 4;
    int stride = gridDim.x * blockDim.x;
    for (int i = blockIdx.x * blockDim.x + threadIdx.x; i < n4; i += stride) {
        float4 v = H[i];
        Hh[i * 2]     = __floats2half2_rn(v.x, v.y);
        Hh[i * 2 + 1] = __floats2half2_rn(v.z, v.w);
    }
}

// ---------------------------------------------------------------------------
// Prep 2: transpose+convert Wq and Wo (4096x4096) -> fp16 [N][K] via blockIdx.z
// ---------------------------------------------------------------------------
__global__ void prep_transpose_QO(const float* __restrict__ Wq,
                                  const float* __restrict__ Wo,
                                  __half* __restrict__ Wh,
                                  __half* __restrict__ Woh)
{
    __shared__ float tile[32][33];
    const float* W = blockIdx.z ? Wo : Wq;
    __half* dst    = blockIdx.z ? Woh : Wh;
    const int N = 4096, K = 4096;
    int x = blockIdx.x * 32 + threadIdx.x;
#pragma unroll
    for (int j = 0; j < 4; j++) {
        int y = blockIdx.y * 32 + threadIdx.y + j * 8;
        tile[threadIdx.y + j * 8][threadIdx.x] = W[(size_t)y * N + x];
    }
    __syncthreads();
    int k = blockIdx.y * 32 + threadIdx.x;
#pragma unroll
    for (int j = 0; j < 4; j++) {
        int n = blockIdx.x * 32 + threadIdx.y + j * 8;
        dst[(size_t)n * K + k] = __float2half_rn(tile[threadIdx.x][threadIdx.y + j * 8]);
    }
}

// ---------------------------------------------------------------------------
// Prep 3: transpose+convert Wk (rows 4096..) / Wv (rows 5120..) via blockIdx.z
// ---------------------------------------------------------------------------
__global__ void prep_transpose_KV(const float* __restrict__ Wk,
                                  const float* __restrict__ Wv,
                                  __half* __restrict__ Wh)
{
    __shared__ float tile[32][33];
    const float* W = blockIdx.z ? Wv : Wk;
    const int rowOff = blockIdx.z ? V_OFF : K_OFF;
    const int N = 1024, K = 4096;
    int x = blockIdx.x * 32 + threadIdx.x;
#pragma unroll
    for (int j = 0; j < 4; j++) {
        int y = blockIdx.y * 32 + threadIdx.y + j * 8;
        tile[threadIdx.y + j * 8][threadIdx.x] = W[(size_t)y * N + x];
    }
    __syncthreads();
    int k = blockIdx.y * 32 + threadIdx.x;
#pragma unroll
    for (int j = 0; j < 4; j++) {
        int n = blockIdx.x * 32 + threadIdx.y + j * 8;
        Wh[(size_t)(rowOff + n) * K + k] = __float2half_rn(tile[threadIdx.x][threadIdx.y + j * 8]);
    }
}

// ---------------------------------------------------------------------------
// FP16 tensor GEMM: C[M,N] = A[M,K] @ Bt[N,K]^T, fp32 accumulate.
// CTA tile 128x128x64, 256 threads (8 warps: 2m x 4n, warp 64x32), 2 CTAs/SM.
// 3-stage cp.async; both operands via ldmatrix (row stride 72 fp16 = 144 B,
// conflict-free: start-bank walk 4i mod 32). mma.m16n8k16.f16 (K=16/instr).
// smem/stage: A 128x72 + B 128x72 fp16 = 36,864 B; 3 stages = 110,592 B.
// ---------------------------------------------------------------------------
#define GEMMH_SMEM (3 * 2 * 128 * 72 * 2)

__global__ __launch_bounds__(256, 2) void h16gemm(const __half* __restrict__ A,
                                                  const __half* __restrict__ Bt,
                                                  float* __restrict__ C,
                                                  int M, int N, int K)
{
    extern __shared__ __half smh[];
    const int tid  = threadIdx.x;
    const int wid  = tid >> 5;
    const int lane = tid & 31;
    const int g    = lane >> 2;
    const int tg   = lane & 3;
    const int wm   = (wid >> 2) * 64;   // 0 or 64
    const int wn   = (wid & 3) * 32;    // 0,32,64,96
    const int bm   = blockIdx.y * 128;
    const int bn   = blockIdx.x * 128;

    const __half* Ab = A  + (size_t)bm * K;
    const __half* Bb = Bt + (size_t)bn * K;

    // ldmatrix lane offset (bytes): row (L&15)*144, k-half (L>>4)*16
    const unsigned lane_off = ((lane & 15) * 144) + ((lane >> 4) * 16);

    float acc[4][4][4];
#pragma unroll
    for (int mt = 0; mt < 4; mt++)
#pragma unroll
        for (int nt = 0; nt < 4; nt++)
#pragma unroll
            for (int i = 0; i < 4; i++) acc[mt][nt][i] = 0.f;

    const int ntiles = K >> 6;           // BK = 64

    auto issue = [&](int t) {
        __half* As_ = smh + (t % 3) * 18432;     // stage = 2*128*72 fp16
        __half* Bs_ = As_ + 9216;
        const int kt = t << 6;
#pragma unroll
        for (int i_ = 0; i_ < 4; i_++) {
            int ch = tid + i_ * 256;             // 0..1023
            int r = ch >> 3, c = ch & 7;         // row, 16B-chunk (8 fp16)
            cp_async16(As_ + r * 72 + c * 8, Ab + (size_t)r * K + kt + c * 8);
            cp_async16(Bs_ + r * 72 + c * 8, Bb + (size_t)r * K + kt + c * 8);
        }
        asm volatile("cp.async.commit_group;");
    };

    issue(0);
    issue(1);

    for (int t = 0; t < ntiles; t++) {
        if (t == ntiles - 1) asm volatile("cp.async.wait_group 0;");
        else                 asm volatile("cp.async.wait_group 1;");
        __syncthreads();
        if (t + 2 < ntiles) issue(t + 2);

        const __half* As_ = smh + (t % 3) * 18432;
        const __half* Bs_ = As_ + 9216;
        const unsigned a_base = (unsigned)__cvta_generic_to_shared(As_) + lane_off;
        const unsigned b_base = (unsigned)__cvta_generic_to_shared(Bs_) + lane_off;

#pragma unroll
        for (int kk = 0; kk < 64; kk += 16) {
            unsigned af[4][4], bq[2][4];
#pragma unroll
            for (int mt = 0; mt < 4; mt++)
                ldsm_x4(af[mt], a_base + (wm + mt * 16) * 144 + kk * 2);
#pragma unroll
            for (int np = 0; np < 2; np++)
                ldsm_x4(bq[np], b_base + (wn + np * 16) * 144 + kk * 2);
            // bq[np]: m0 = n+0..7 k-lo | m1 = n+8..15 k-lo | m2 = n+0..7 k-hi | m3 = n+8..15 k-hi
#pragma unroll
            for (int mt = 0; mt < 4; mt++)
#pragma unroll
                for (int nt = 0; nt < 4; nt++) {
                    unsigned b[2] = { bq[nt >> 1][nt & 1], bq[nt >> 1][(nt & 1) + 2] };
                    mma_f16(acc[mt][nt], af[mt], b);
                }
        }
    }

#pragma unroll
    for (int mt = 0; mt < 4; mt++) {
#pragma unroll
        for (int nt = 0; nt < 4; nt++) {
            int row = bm + wm + mt * 16 + g;
            int col = bn + wn + nt * 8 + tg * 2;
            *(float2*)&C[(size_t)row * N + col]       = make_float2(acc[mt][nt][0], acc[mt][nt][1]);
            *(float2*)&C[(size_t)(row + 8) * N + col] = make_float2(acc[mt][nt][2], acc[mt][nt][3]);
        }
    }
}

// ---------------------------------------------------------------------------
// RoPE in-place on fused qkv. Q pre-scaled by 1/sqrt(D)*log2(e). tf32 rounding.
// ---------------------------------------------------------------------------
__global__ void rope_round_kernel(const float* __restrict__ cosp,
                                  const float* __restrict__ sinp)
{
    const int t = blockIdx.x;
    float* rowp = &g_qkv[(size_t)t * QKV_N];
    for (int p = threadIdx.x; p < (HQ + HKV) * 64; p += blockDim.x) {
        int h = p >> 6;
        int d = p & 63;
        float c = cosp[t * DH + d];
        float s = sinp[t * DH + d];
        float* base = (h < HQ) ? rowp + h * DH : rowp + K_OFF + (h - HQ) * DH;
        float sc = (h < HQ) ? QSCALE_F : 1.0f;
        float x1 = base[d];
        float x2 = base[d + 64];
        base[d]      = tf32f((x1 * c - x2 * s) * sc);
        base[d + 64] = tf32f((x2 * c + x1 * s) * sc);
    }
    for (int i = threadIdx.x; i < HKV * DH; i += blockDim.x) {
        float* pv = rowp + V_OFF + i;
        *pv = tf32f(*pv);
    }
}

// ---------------------------------------------------------------------------
// Tensor-core flash attention (R12 exact, tf32): 64 queries x 1 head,
// 128 threads, 2 CTAs/SM; no-max exp2 softmax; 25% poly / 75% MUFU.
// Only change: epilogue writes fp16 O (feeds fp16 Wo GEMM; same 2^-11 ulp).
// ---------------------------------------------------------------------------
#define ATT_SMEM_BYTES ((64 * 132 + 64 * 136 + 64 * 68) * 4)

__global__ __launch_bounds__(128, 2) void attn_mma_kernel()
{
    extern __shared__ float smf[];
    float* Ks = smf;                 // [64][132]
    float* Vs = smf + 64 * 132;      // [64][136]
    float* Ps = Vs + 64 * 136;       // [64][68]

    const int h    = blockIdx.y;
    const int kvh  = h / GROUPS;
    const int qi   = gridDim.x - 1 - blockIdx.x;   // long CTAs first
    const int q0   = qi * 64;
    const int tid  = threadIdx.x;
    const int w    = tid >> 5;
    const int lane = tid & 31;
    const int g    = lane >> 2;
    const int tg   = lane & 3;
    const int wrow = w * 16;

    const unsigned k_lane_off = (((lane & 15) * 132 + (lane >> 4) * 4) << 2);
    const unsigned p_lane_off = (((lane & 15) * 68  + (lane >> 4) * 4) << 2);
    const unsigned ks_smem = (unsigned)__cvta_generic_to_shared(Ks);
    const unsigned ps_base = (unsigned)__cvta_generic_to_shared(Ps) + p_lane_off
                             + ((wrow * 68) << 2);

    for (int idx = tid; idx < 64 * 32; idx += 128) {
        int r = idx >> 5, c4 = (idx & 31) << 2;
        *(float4*)&Ks[r * 132 + c4] =
            *(const float4*)&g_qkv[(size_t)(q0 + r) * QKV_N + h * DH + c4];
    }
    __syncthreads();
    unsigned qf[16][4];
    {
        const unsigned q_base = ks_smem + k_lane_off + ((wrow * 132) << 2);
#pragma unroll
        for (int kk8 = 0; kk8 < 16; kk8++)
            ldsm_x4(qf[kk8], q_base + ((kk8 * 8) << 2));
    }
    __syncthreads();

    float acc_o[16][4];
#pragma unroll
    for (int nt = 0; nt < 16; nt++)
#pragma unroll
        for (int i = 0; i < 4; i++) acc_o[nt][i] = 0.f;
    float l0 = 0.f, l1 = 0.f;

    for (int k0 = 0; k0 <= q0; k0 += 64) {
        for (int idx = tid; idx < 64 * 32; idx += 128) {
            int r = idx >> 5, c4 = (idx & 31) << 2;
            size_t off = (size_t)(k0 + r) * QKV_N + kvh * DH + c4;
            *(float4*)&Ks[r * 132 + c4] = *(const float4*)&g_qkv[off + K_OFF];
            *(float4*)&Vs[r * 136 + c4] = *(const float4*)&g_qkv[off + V_OFF];
        }
        __syncthreads();

        float acc_s[8][4];
#pragma unroll
        for (int nt = 0; nt < 8; nt++)
#pragma unroll
            for (int i = 0; i < 4; i++) acc_s[nt][i] = 0.f;
        const unsigned kb_base = ks_smem + k_lane_off;
#pragma unroll
        for (int kk8 = 0; kk8 < 16; kk8++) {
#pragma unroll
            for (int ntp = 0; ntp < 4; ntp++) {
                unsigned kq[4];
                ldsm_x4(kq, kb_base + (((ntp * 16 * 132) + kk8 * 8) << 2));
                unsigned b0[2] = { kq[0], kq[2] };
                unsigned b1[2] = { kq[1], kq[3] };
                mma_tf32(acc_s[2 * ntp],     qf[kk8], b0);
                mma_tf32(acc_s[2 * ntp + 1], qf[kk8], b1);
            }
        }

        const bool diag = (k0 == q0);
        const int r0 = q0 + wrow + g, r1 = r0 + 8;
#pragma unroll
        for (int nt = 0; nt < 8; nt++) {
            float x0 = acc_s[nt][0] - 32.f;
            float x1 = acc_s[nt][1] - 32.f;
            float x2 = acc_s[nt][2] - 32.f;
            float x3 = acc_s[nt][3] - 32.f;
            if (diag) {
                int col0 = k0 + nt * 8 + tg * 2;
                if (col0     > r0) x0 = -1e30f;
                if (col0 + 1 > r0) x1 = -1e30f;
                if (col0     > r1) x2 = -1e30f;
                if (col0 + 1 > r1) x3 = -1e30f;
            }
            float p0, p1, p2, p3;
            if (nt < 2) {
                p0 = exp2_poly(x0); p1 = exp2_poly(x1);
                p2 = exp2_poly(x2); p3 = exp2_poly(x3);
            } else {
                p0 = ex2_mufu(x0); p1 = ex2_mufu(x1);
                p2 = ex2_mufu(x2); p3 = ex2_mufu(x3);
            }
            l0 += p0 + p1;
            l1 += p2 + p3;
            *(float2*)&Ps[(wrow + g) * 68 + nt * 8 + tg * 2]     = make_float2(tf32f(p0), tf32f(p1));
            *(float2*)&Ps[(wrow + g + 8) * 68 + nt * 8 + tg * 2] = make_float2(tf32f(p2), tf32f(p3));
        }
        __syncwarp();

#pragma unroll
        for (int kk8 = 0; kk8 < 8; kk8++) {
            unsigned a[4];
            ldsm_x4(a, ps_base + ((kk8 * 8) << 2));
#pragma unroll
            for (int nt = 0; nt < 16; nt++) {
                unsigned b[2];
                b[0] = __float_as_uint(Vs[(kk8 * 8 + tg) * 136 + nt * 8 + g]);
                b[1] = __float_as_uint(Vs[(kk8 * 8 + tg + 4) * 136 + nt * 8 + g]);
                mma_tf32(acc_o[nt], a, b);
            }
        }
        __syncthreads();
    }

    l0 += __shfl_xor_sync(0xffffffffu, l0, 1);
    l0 += __shfl_xor_sync(0xffffffffu, l0, 2);
    l1 += __shfl_xor_sync(0xffffffffu, l1, 1);
    l1 += __shfl_xor_sync(0xffffffffu, l1, 2);
    const float inv0 = 1.f / l0;
    const float inv1 = 1.f / l1;

    const int row0 = q0 + wrow + g, row1 = row0 + 8;
#pragma unroll
    for (int nt = 0; nt < 16; nt++) {
        int col = h * DH + nt * 8 + tg * 2;
        *(__half2*)&g_attnh[(size_t)row0 * (HQ * DH) + col] =
            __floats2half2_rn(acc_o[nt][0] * inv0, acc_o[nt][1] * inv0);
        *(__half2*)&g_attnh[(size_t)row1 * (HQ * DH) + col] =
            __floats2half2_rn(acc_o[nt][2] * inv1, acc_o[nt][3] * inv1);
    }
}

// ---------------------------------------------------------------------------
// Launch pipeline (7 launches). Inputs:
// 0 H | 1 pos | 2 cos | 3 sin | 4 Wq | 5 Wk | 6 Wv | 7 Wo
// ---------------------------------------------------------------------------
extern "C" void kernel_launch(void* const* d_in, const int* in_sizes, int n_in,
                              void* d_out, int out_size)
{
    const float* H    = (const float*)d_in[0];
    const float* cosp = (const float*)d_in[2];
    const float* sinp = (const float*)d_in[3];
    const float* Wq   = (const float*)d_in[4];
    const float* Wk   = (const float*)d_in[5];
    const float* Wv   = (const float*)d_in[6];
    const float* Wo   = (const float*)d_in[7];
    float* out = (float*)d_out;

    float *qkv;
    __half *attnh, *Hh, *Wh, *Woh;
    cudaGetSymbolAddress((void**)&qkv,   g_qkv);
    cudaGetSymbolAddress((void**)&attnh, g_attnh);
    cudaGetSymbolAddress((void**)&Hh,    g_Hh);
    cudaGetSymbolAddress((void**)&Wh,    g_Wh);
    cudaGetSymbolAddress((void**)&Woh,   g_Woh);

    cudaFuncSetAttribute(h16gemm, cudaFuncAttributeMaxDynamicSharedMemorySize, GEMMH_SMEM);
    cudaFuncSetAttribute(attn_mma_kernel, cudaFuncAttributeMaxDynamicSharedMemorySize, ATT_SMEM_BYTES);

    // Prep (3 launches)
    prep_H_half<<<512, 256>>>((const float4*)H, (__half2*)Hh);
    prep_transpose_QO<<<dim3(128, 128, 2), dim3(32, 8)>>>(Wq, Wo, Wh, Woh);
    prep_transpose_KV<<<dim3(32, 128, 2), dim3(32, 8)>>>(Wk, Wv, Wh);

    // Fused QKV projection, fp16 tensor cores (launch 4)
    h16gemm<<<dim3(QKV_N / 128, T_SEQ / 128), 256, GEMMH_SMEM>>>(
        Hh, Wh, qkv, T_SEQ, QKV_N, HID);

    // RoPE (launch 5)
    rope_round_kernel<<<T_SEQ, 256>>>(cosp, sinp);

    // Attention (launch 6)
    attn_mma_kernel<<<dim3(T_SEQ / 64, HQ), 128, ATT_SMEM_BYTES>>>();

    // Output projection, fp16 tensor cores (launch 7)
    h16gemm<<<dim3(HID / 128, T_SEQ / 128), 256, GEMMH_SMEM>>>(
        attnh, Woh, out, T_SEQ, HID, HQ * DH);
}

// round 14
// speedup vs baseline: 2.2583x; 1.0500x over previous
#include <cuda_runtime.h>
#include <cuda_bf16.h>
#include <cuda_fp16.h>
#include <math.h>

#define T_SEQ 2048
#define HID   4096
#define HQ    32
#define HKV   8
#define DH    128
#define GROUPS (HQ / HKV)
#define QKV_N 6144                      // 4096 q | 1024 k | 1024 v
#define K_OFF 4096
#define V_OFF 5120

// q pre-scale: 1/sqrt(128) * log2(e)  (softmax runs in exp2 domain)
#define QSCALE_F ((float)(0.08838834764831845 * 1.4426950408889634))

// ---------------- device scratch (no allocs allowed) ----------------
__device__ float  g_qkv[T_SEQ * QKV_N];       // 50 MB  fused q|k|v (fp32, GEMM out)
__device__ __half g_qh [T_SEQ * HQ * DH];     // 16 MB  roped+scaled Q (fp16)
__device__ __half g_kh [T_SEQ * HKV * DH];    // 4 MB   roped K (fp16)
__device__ __half g_attnh[T_SEQ * HQ * DH];   // 16 MB  attention out (fp16)
__device__ __half g_Hh [T_SEQ * HID];         // 16 MB  fp16 H [M][K]
__device__ __half g_Wh [QKV_N * HID];         // 48 MB  fp16 [Wq|Wk|Wv] transposed [N][K]
__device__ __half g_Woh[HID * HQ * DH];       // 32 MB  fp16 Wo transposed [N][K]

__device__ __forceinline__ unsigned tf32_cvt(float x) {
    unsigned r;
    asm("cvt.rna.tf32.f32 %0, %1;" : "=r"(r) : "f"(x));
    return r;
}
__device__ __forceinline__ float tf32f(float x) { return __uint_as_float(tf32_cvt(x)); }

__device__ __forceinline__ void mma_tf32(float* d, const unsigned* a, const unsigned* b) {
    asm volatile(
        "mma.sync.aligned.m16n8k8.row.col.f32.tf32.tf32.f32 "
        "{%0,%1,%2,%3}, {%4,%5,%6,%7}, {%8,%9}, {%0,%1,%2,%3};"
        : "+f"(d[0]), "+f"(d[1]), "+f"(d[2]), "+f"(d[3])
        : "r"(a[0]), "r"(a[1]), "r"(a[2]), "r"(a[3]), "r"(b[0]), "r"(b[1]));
}

__device__ __forceinline__ void mma_f16(float* d, const unsigned* a, const unsigned* b) {
    asm volatile(
        "mma.sync.aligned.m16n8k16.row.col.f32.f16.f16.f32 "
        "{%0,%1,%2,%3}, {%4,%5,%6,%7}, {%8,%9}, {%0,%1,%2,%3};"
        : "+f"(d[0]), "+f"(d[1]), "+f"(d[2]), "+f"(d[3])
        : "r"(a[0]), "r"(a[1]), "r"(a[2]), "r"(a[3]), "r"(b[0]), "r"(b[1]));
}

// ldmatrix x4: lane L supplies the 16B row address of matrix (L>>3).
__device__ __forceinline__ void ldsm_x4(unsigned* r, unsigned a) {
    asm volatile("ldmatrix.sync.aligned.m8n8.x4.shared.b16 {%0,%1,%2,%3}, [%4];"
                 : "=r"(r[0]), "=r"(r[1]), "=r"(r[2]), "=r"(r[3]) : "r"(a));
}

__device__ __forceinline__ void cp_async16(void* smem_dst, const void* gmem_src) {
    unsigned s = (unsigned)__cvta_generic_to_shared(smem_dst);
    asm volatile("cp.async.cg.shared.global [%0], [%1], 16;" :: "r"(s), "l"(gmem_src));
}

// MUFU exp2
__device__ __forceinline__ float ex2_mufu(float x) {
    float y;
    asm("ex2.approx.ftz.f32 %0, %1;" : "=f"(y) : "f"(x));
    return y;
}

// FMA-pipe exp2: minimax on f in [-0.5, 0.5], ~1e-7 rel err.
__device__ __forceinline__ float exp2_poly(float x) {
    x = fmaxf(x, -120.f);
    float t = x + 12582912.f;
    float i = t - 12582912.f;
    float f = x - i;
    float p = 1.535336188319500e-4f;
    p = fmaf(p, f, 1.339887440266574e-3f);
    p = fmaf(p, f, 9.618437357674640e-3f);
    p = fmaf(p, f, 5.550332471162809e-2f);
    p = fmaf(p, f, 2.402264791363012e-1f);
    p = fmaf(p, f, 6.931472028550421e-1f);
    p = fmaf(p, f, 1.0f);
    int ii = (int)i;
    return p * __int_as_float((ii + 127) << 23);
}

// ---------------------------------------------------------------------------
// Prep 1: convert H to fp16 [M][K]
// ---------------------------------------------------------------------------
__global__ void prep_H_half(const float4* __restrict__ H, __half2* __restrict__ Hh)
{
    const int n4 = T_SEQ * HID / 4;
    int stride = gridDim.x * blockDim.x;
    for (int i = blockIdx.x * blockDim.x + threadIdx.x; i < n4; i += stride) {
        float4 v = H[i];
        Hh[i * 2]     = __floats2half2_rn(v.x, v.y);
        Hh[i * 2 + 1] = __floats2half2_rn(v.z, v.w);
    }
}

// ---------------------------------------------------------------------------
// Prep 2: transpose+convert Wq and Wo (4096x4096) -> fp16 [N][K] via blockIdx.z
// ---------------------------------------------------------------------------
__global__ void prep_transpose_QO(const float* __restrict__ Wq,
                                  const float* __restrict__ Wo,
                                  __half* __restrict__ Wh,
                                  __half* __restrict__ Woh)
{
    __shared__ float tile[32][33];
    const float* W = blockIdx.z ? Wo : Wq;
    __half* dst    = blockIdx.z ? Woh : Wh;
    const int N = 4096, K = 4096;
    int x = blockIdx.x * 32 + threadIdx.x;
#pragma unroll
    for (int j = 0; j < 4; j++) {
        int y = blockIdx.y * 32 + threadIdx.y + j * 8;
        tile[threadIdx.y + j * 8][threadIdx.x] = W[(size_t)y * N + x];
    }
    __syncthreads();
    int k = blockIdx.y * 32 + threadIdx.x;
#pragma unroll
    for (int j = 0; j < 4; j++) {
        int n = blockIdx.x * 32 + threadIdx.y + j * 8;
        dst[(size_t)n * K + k] = __float2half_rn(tile[threadIdx.x][threadIdx.y + j * 8]);
    }
}

// ---------------------------------------------------------------------------
// Prep 3: transpose+convert Wk (rows 4096..) / Wv (rows 5120..) via blockIdx.z
// ---------------------------------------------------------------------------
__global__ void prep_transpose_KV(const float* __restrict__ Wk,
                                  const float* __restrict__ Wv,
                                  __half* __restrict__ Wh)
{
    __shared__ float tile[32][33];
    const float* W = blockIdx.z ? Wv : Wk;
    const int rowOff = blockIdx.z ? V_OFF : K_OFF;
    const int N = 1024, K = 4096;
    int x = blockIdx.x * 32 + threadIdx.x;
#pragma unroll
    for (int j = 0; j < 4; j++) {
        int y = blockIdx.y * 32 + threadIdx.y + j * 8;
        tile[threadIdx.y + j * 8][threadIdx.x] = W[(size_t)y * N + x];
    }
    __syncthreads();
    int k = blockIdx.y * 32 + threadIdx.x;
#pragma unroll
    for (int j = 0; j < 4; j++) {
        int n = blockIdx.x * 32 + threadIdx.y + j * 8;
        Wh[(size_t)(rowOff + n) * K + k] = __float2half_rn(tile[threadIdx.x][threadIdx.y + j * 8]);
    }
}

// ---------------------------------------------------------------------------
// FP16 tensor GEMM (R13 exact): C[M,N] = A[M,K] @ Bt[N,K]^T, fp32 accumulate.
// CTA tile 128x128x64, 256 threads, 2 CTAs/SM, 3-stage cp.async, ldmatrix both.
// ---------------------------------------------------------------------------
#define GEMMH_SMEM (3 * 2 * 128 * 72 * 2)

__global__ __launch_bounds__(256, 2) void h16gemm(const __half* __restrict__ A,
                                                  const __half* __restrict__ Bt,
                                                  float* __restrict__ C,
                                                  int M, int N, int K)
{
    extern __shared__ __half smh[];
    const int tid  = threadIdx.x;
    const int wid  = tid >> 5;
    const int lane = tid & 31;
    const int g    = lane >> 2;
    const int tg   = lane & 3;
    const int wm   = (wid >> 2) * 64;
    const int wn   = (wid & 3) * 32;
    const int bm   = blockIdx.y * 128;
    const int bn   = blockIdx.x * 128;

    const __half* Ab = A  + (size_t)bm * K;
    const __half* Bb = Bt + (size_t)bn * K;

    const unsigned lane_off = ((lane & 15) * 144) + ((lane >> 4) * 16);

    float acc[4][4][4];
#pragma unroll
    for (int mt = 0; mt < 4; mt++)
#pragma unroll
        for (int nt = 0; nt < 4; nt++)
#pragma unroll
            for (int i = 0; i < 4; i++) acc[mt][nt][i] = 0.f;

    const int ntiles = K >> 6;

    auto issue = [&](int t) {
        __half* As_ = smh + (t % 3) * 18432;
        __half* Bs_ = As_ + 9216;
        const int kt = t << 6;
#pragma unroll
        for (int i_ = 0; i_ < 4; i_++) {
            int ch = tid + i_ * 256;
            int r = ch >> 3, c = ch & 7;
            cp_async16(As_ + r * 72 + c * 8, Ab + (size_t)r * K + kt + c * 8);
            cp_async16(Bs_ + r * 72 + c * 8, Bb + (size_t)r * K + kt + c * 8);
        }
        asm volatile("cp.async.commit_group;");
    };

    issue(0);
    issue(1);

    for (int t = 0; t < ntiles; t++) {
        if (t == ntiles - 1) asm volatile("cp.async.wait_group 0;");
        else                 asm volatile("cp.async.wait_group 1;");
        __syncthreads();
        if (t + 2 < ntiles) issue(t + 2);

        const __half* As_ = smh + (t % 3) * 18432;
        const __half* Bs_ = As_ + 9216;
        const unsigned a_base = (unsigned)__cvta_generic_to_shared(As_) + lane_off;
        const unsigned b_base = (unsigned)__cvta_generic_to_shared(Bs_) + lane_off;

#pragma unroll
        for (int kk = 0; kk < 64; kk += 16) {
            unsigned af[4][4], bq[2][4];
#pragma unroll
            for (int mt = 0; mt < 4; mt++)
                ldsm_x4(af[mt], a_base + (wm + mt * 16) * 144 + kk * 2);
#pragma unroll
            for (int np = 0; np < 2; np++)
                ldsm_x4(bq[np], b_base + (wn + np * 16) * 144 + kk * 2);
#pragma unroll
            for (int mt = 0; mt < 4; mt++)
#pragma unroll
                for (int nt = 0; nt < 4; nt++) {
                    unsigned b[2] = { bq[nt >> 1][nt & 1], bq[nt >> 1][(nt & 1) + 2] };
                    mma_f16(acc[mt][nt], af[mt], b);
                }
        }
    }

#pragma unroll
    for (int mt = 0; mt < 4; mt++) {
#pragma unroll
        for (int nt = 0; nt < 4; nt++) {
            int row = bm + wm + mt * 16 + g;
            int col = bn + wn + nt * 8 + tg * 2;
            *(float2*)&C[(size_t)row * N + col]       = make_float2(acc[mt][nt][0], acc[mt][nt][1]);
            *(float2*)&C[(size_t)(row + 8) * N + col] = make_float2(acc[mt][nt][2], acc[mt][nt][3]);
        }
    }
}

// ---------------------------------------------------------------------------
// RoPE: reads fused qkv (fp32), writes Q (scaled) and K as fp16, V tf32 in place.
// ---------------------------------------------------------------------------
__global__ void rope_split_kernel(const float* __restrict__ cosp,
                                  const float* __restrict__ sinp)
{
    const int t = blockIdx.x;
    const float* rowp = &g_qkv[(size_t)t * QKV_N];
    for (int p = threadIdx.x; p < (HQ + HKV) * 64; p += blockDim.x) {
        int h = p >> 6;
        int d = p & 63;
        float c = cosp[t * DH + d];
        float s = sinp[t * DH + d];
        if (h < HQ) {
            const float* base = rowp + h * DH;
            float x1 = base[d], x2 = base[d + 64];
            __half* qb = &g_qh[(size_t)t * (HQ * DH) + h * DH];
            qb[d]      = __float2half_rn((x1 * c - x2 * s) * QSCALE_F);
            qb[d + 64] = __float2half_rn((x2 * c + x1 * s) * QSCALE_F);
        } else {
            const float* base = rowp + K_OFF + (h - HQ) * DH;
            float x1 = base[d], x2 = base[d + 64];
            __half* kb = &g_kh[(size_t)t * (HKV * DH) + (h - HQ) * DH];
            kb[d]      = __float2half_rn(x1 * c - x2 * s);
            kb[d + 64] = __float2half_rn(x2 * c + x1 * s);
        }
    }
    for (int i = threadIdx.x; i < HKV * DH; i += blockDim.x) {
        float* pv = (float*)rowp + V_OFF + i;
        *pv = tf32f(*pv);
    }
}

// ---------------------------------------------------------------------------
// Flash attention: fp16 Q@K (m16n8k16) + tf32 P@V (m16n8k8).
// 64 queries x 1 head, 128 threads, 3 CTAs/SM (smem 69,632 B).
// No-max exp2 softmax; 25% poly / 75% MUFU.
// smem: Ksh fp16[64][136] (17408 B) | Vs f32[64][136] (34816 B) | Ps f32[64][68]
// ---------------------------------------------------------------------------
#define ATT_SMEM_BYTES (17408 + 34816 + 17408)

__global__ __launch_bounds__(128, 3) void attn_mma_kernel()
{
    extern __shared__ char smb[];
    __half* Ksh = (__half*)smb;                  // [64][136] fp16
    float*  Vs  = (float*)(smb + 17408);         // [64][136] fp32
    float*  Ps  = (float*)(smb + 52224);         // [64][68]  fp32

    const int h    = blockIdx.y;
    const int kvh  = h / GROUPS;
    const int qi   = gridDim.x - 1 - blockIdx.x;   // long CTAs first
    const int q0   = qi * 64;
    const int tid  = threadIdx.x;
    const int w    = tid >> 5;
    const int lane = tid & 31;
    const int g    = lane >> 2;
    const int tg   = lane & 3;
    const int wrow = w * 16;

    // fp16 ldmatrix lane offset (bytes): row (L&15)*272, k-half (L>>4)*16
    const unsigned h_lane_off = ((lane & 15) * 272) + ((lane >> 4) * 16);
    const unsigned p_lane_off = (((lane & 15) * 68 + (lane >> 4) * 4) << 2);
    const unsigned ksh_smem = (unsigned)__cvta_generic_to_shared(Ksh);
    const unsigned ps_base  = (unsigned)__cvta_generic_to_shared(Ps) + p_lane_off
                              + ((wrow * 68) << 2);

    // ---- stage Q tile (fp16) into Ksh; move to fragments
    for (int idx = tid; idx < 64 * 16; idx += 128) {
        int r = idx >> 4, c8 = (idx & 15) << 3;
        *(float4*)&Ksh[r * 136 + c8] =
            *(const float4*)&g_qh[(size_t)(q0 + r) * (HQ * DH) + h * DH + c8];
    }
    __syncthreads();
    unsigned qf[8][4];
    {
        const unsigned q_base = ksh_smem + h_lane_off + (unsigned)(wrow * 272);
#pragma unroll
        for (int kk = 0; kk < 8; kk++)
            ldsm_x4(qf[kk], q_base + kk * 32);
    }
    __syncthreads();

    float acc_o[16][4];
#pragma unroll
    for (int nt = 0; nt < 16; nt++)
#pragma unroll
        for (int i = 0; i < 4; i++) acc_o[nt][i] = 0.f;
    float l0 = 0.f, l1 = 0.f;

    for (int k0 = 0; k0 <= q0; k0 += 64) {
        // load K (fp16) + V (fp32) tiles
        for (int idx = tid; idx < 64 * 16 + 64 * 32; idx += 128) {
            if (idx < 64 * 16) {
                int r = idx >> 4, c8 = (idx & 15) << 3;
                *(float4*)&Ksh[r * 136 + c8] =
                    *(const float4*)&g_kh[(size_t)(k0 + r) * (HKV * DH) + kvh * DH + c8];
            } else {
                int j = idx - 64 * 16;
                int r = j >> 5, c4 = (j & 31) << 2;
                *(float4*)&Vs[r * 136 + c4] =
                    *(const float4*)&g_qkv[(size_t)(k0 + r) * QKV_N + V_OFF + kvh * DH + c4];
            }
        }
        __syncthreads();

        // ---- S2 = Q @ K^T  (fp16 mma, 64 instrs/tile)
        float acc_s[8][4];
#pragma unroll
        for (int nt = 0; nt < 8; nt++)
#pragma unroll
            for (int i = 0; i < 4; i++) acc_s[nt][i] = 0.f;
        const unsigned kb_base = ksh_smem + h_lane_off;
#pragma unroll
        for (int kk = 0; kk < 8; kk++) {
#pragma unroll
            for (int ntp = 0; ntp < 4; ntp++) {
                unsigned kq[4];
                ldsm_x4(kq, kb_base + (unsigned)(ntp * 16 * 272) + kk * 32);
                unsigned b0[2] = { kq[0], kq[2] };
                unsigned b1[2] = { kq[1], kq[3] };
                mma_f16(acc_s[2 * ntp],     qf[kk], b0);
                mma_f16(acc_s[2 * ntp + 1], qf[kk], b1);
            }
        }

        // ---- p = 2^(s2 - 32); causal mask on diagonal tile
        const bool diag = (k0 == q0);
        const int r0 = q0 + wrow + g, r1 = r0 + 8;
#pragma unroll
        for (int nt = 0; nt < 8; nt++) {
            float x0 = acc_s[nt][0] - 32.f;
            float x1 = acc_s[nt][1] - 32.f;
            float x2 = acc_s[nt][2] - 32.f;
            float x3 = acc_s[nt][3] - 32.f;
            if (diag) {
                int col0 = k0 + nt * 8 + tg * 2;
                if (col0     > r0) x0 = -1e30f;
                if (col0 + 1 > r0) x1 = -1e30f;
                if (col0     > r1) x2 = -1e30f;
                if (col0 + 1 > r1) x3 = -1e30f;
            }
            float p0, p1, p2, p3;
            if (nt < 2) {                      // 25% on FMA pipe
                p0 = exp2_poly(x0); p1 = exp2_poly(x1);
                p2 = exp2_poly(x2); p3 = exp2_poly(x3);
            } else {                           // 75% on MUFU
                p0 = ex2_mufu(x0); p1 = ex2_mufu(x1);
                p2 = ex2_mufu(x2); p3 = ex2_mufu(x3);
            }
            l0 += p0 + p1;
            l1 += p2 + p3;
            *(float2*)&Ps[(wrow + g) * 68 + nt * 8 + tg * 2]     = make_float2(tf32f(p0), tf32f(p1));
            *(float2*)&Ps[(wrow + g + 8) * 68 + nt * 8 + tg * 2] = make_float2(tf32f(p2), tf32f(p3));
        }
        __syncwarp();   // Ps rows are warp-private

        // ---- O += P @ V  (tf32 mma; P needs fp32 exponent range)
#pragma unroll
        for (int kk8 = 0; kk8 < 8; kk8++) {
            unsigned a[4];
            ldsm_x4(a, ps_base + ((kk8 * 8) << 2));
#pragma unroll
            for (int nt = 0; nt < 16; nt++) {
                unsigned b[2];
                b[0] = __float_as_uint(Vs[(kk8 * 8 + tg) * 136 + nt * 8 + g]);
                b[1] = __float_as_uint(Vs[(kk8 * 8 + tg + 4) * 136 + nt * 8 + g]);
                mma_tf32(acc_o[nt], a, b);
            }
        }
        __syncthreads();
    }

    l0 += __shfl_xor_sync(0xffffffffu, l0, 1);
    l0 += __shfl_xor_sync(0xffffffffu, l0, 2);
    l1 += __shfl_xor_sync(0xffffffffu, l1, 1);
    l1 += __shfl_xor_sync(0xffffffffu, l1, 2);
    const float inv0 = 1.f / l0;
    const float inv1 = 1.f / l1;

    const int row0 = q0 + wrow + g, row1 = row0 + 8;
#pragma unroll
    for (int nt = 0; nt < 16; nt++) {
        int col = h * DH + nt * 8 + tg * 2;
        *(__half2*)&g_attnh[(size_t)row0 * (HQ * DH) + col] =
            __floats2half2_rn(acc_o[nt][0] * inv0, acc_o[nt][1] * inv0);
        *(__half2*)&g_attnh[(size_t)row1 * (HQ * DH) + col] =
            __floats2half2_rn(acc_o[nt][2] * inv1, acc_o[nt][3] * inv1);
    }
}

// ---------------------------------------------------------------------------
// Launch pipeline (7 launches). Inputs:
// 0 H | 1 pos | 2 cos | 3 sin | 4 Wq | 5 Wk | 6 Wv | 7 Wo
// ---------------------------------------------------------------------------
extern "C" void kernel_launch(void* const* d_in, const int* in_sizes, int n_in,
                              void* d_out, int out_size)
{
    const float* H    = (const float*)d_in[0];
    const float* cosp = (const float*)d_in[2];
    const float* sinp = (const float*)d_in[3];
    const float* Wq   = (const float*)d_in[4];
    const float* Wk   = (const float*)d_in[5];
    const float* Wv   = (const float*)d_in[6];
    const float* Wo   = (const float*)d_in[7];
    float* out = (float*)d_out;

    float *qkv;
    __half *attnh, *Hh, *Wh, *Woh;
    cudaGetSymbolAddress((void**)&qkv,   g_qkv);
    cudaGetSymbolAddress((void**)&attnh, g_attnh);
    cudaGetSymbolAddress((void**)&Hh,    g_Hh);
    cudaGetSymbolAddress((void**)&Wh,    g_Wh);
    cudaGetSymbolAddress((void**)&Woh,   g_Woh);

    cudaFuncSetAttribute(h16gemm, cudaFuncAttributeMaxDynamicSharedMemorySize, GEMMH_SMEM);
    cudaFuncSetAttribute(attn_mma_kernel, cudaFuncAttributeMaxDynamicSharedMemorySize, ATT_SMEM_BYTES);

    // Prep (3 launches)
    prep_H_half<<<512, 256>>>((const float4*)H, (__half2*)Hh);
    prep_transpose_QO<<<dim3(128, 128, 2), dim3(32, 8)>>>(Wq, Wo, Wh, Woh);
    prep_transpose_KV<<<dim3(32, 128, 2), dim3(32, 8)>>>(Wk, Wv, Wh);

    // Fused QKV projection, fp16 tensor cores (launch 4)
    h16gemm<<<dim3(QKV_N / 128, T_SEQ / 128), 256, GEMMH_SMEM>>>(
        Hh, Wh, qkv, T_SEQ, QKV_N, HID);

    // RoPE -> fp16 Q/K + tf32 V (launch 5)
    rope_split_kernel<<<T_SEQ, 256>>>(cosp, sinp);

    // Attention: fp16 QK + tf32 PV, 3 CTAs/SM (launch 6)
    attn_mma_kernel<<<dim3(T_SEQ / 64, HQ), 128, ATT_SMEM_BYTES>>>();

    // Output projection, fp16 tensor cores (launch 7)
    h16gemm<<<dim3(HID / 128, T_SEQ / 128), 256, GEMMH_SMEM>>>(
        attnh, Woh, out, T_SEQ, HID, HQ * DH);
}

// round 15
// speedup vs baseline: 2.4675x; 1.0926x over previous
#include <cuda_runtime.h>
#include <cuda_bf16.h>
#include <cuda_fp16.h>
#include <math.h>

#define T_SEQ 2048
#define HID   4096
#define HQ    32
#define HKV   8
#define DH    128
#define GROUPS (HQ / HKV)
#define QKV_N 6144                      // 4096 q | 1024 k | 1024 v
#define K_OFF 4096
#define V_OFF 5120

// q pre-scale: 1/sqrt(128) * log2(e)  (softmax runs in exp2 domain)
#define QSCALE_F ((float)(0.08838834764831845 * 1.4426950408889634))

// ---------------- device scratch (no allocs allowed) ----------------
__device__ float  g_qkv[T_SEQ * QKV_N];       // 50 MB  fused q|k|v (fp32, GEMM out)
__device__ __half g_qh [T_SEQ * HQ * DH];     // 16 MB  roped+scaled Q (fp16)
__device__ __half g_kh [T_SEQ * HKV * DH];    // 4 MB   roped K (fp16)
__device__ __half g_vh [T_SEQ * HKV * DH];    // 4 MB   V (fp16)
__device__ __half g_attnh[T_SEQ * HQ * DH];   // 16 MB  attention out (fp16)
__device__ __half g_Hh [T_SEQ * HID];         // 16 MB  fp16 H [M][K]
__device__ __half g_Wh [QKV_N * HID];         // 48 MB  fp16 [Wq|Wk|Wv] transposed [N][K]
__device__ __half g_Woh[HID * HQ * DH];       // 32 MB  fp16 Wo transposed [N][K]

__device__ __forceinline__ void mma_f16(float* d, const unsigned* a, const unsigned* b) {
    asm volatile(
        "mma.sync.aligned.m16n8k16.row.col.f32.f16.f16.f32 "
        "{%0,%1,%2,%3}, {%4,%5,%6,%7}, {%8,%9}, {%0,%1,%2,%3};"
        : "+f"(d[0]), "+f"(d[1]), "+f"(d[2]), "+f"(d[3])
        : "r"(a[0]), "r"(a[1]), "r"(a[2]), "r"(a[3]), "r"(b[0]), "r"(b[1]));
}

// ldmatrix x4: lane L supplies the 16B row address of matrix (L>>3).
__device__ __forceinline__ void ldsm_x4(unsigned* r, unsigned a) {
    asm volatile("ldmatrix.sync.aligned.m8n8.x4.shared.b16 {%0,%1,%2,%3}, [%4];"
                 : "=r"(r[0]), "=r"(r[1]), "=r"(r[2]), "=r"(r[3]) : "r"(a));
}
// transposed variant (for k-major B tiles): lane L reg j =
// pack(M_j[2*(L&3)][L>>2], M_j[2*(L&3)+1][L>>2]) == fp16 mma b-frag.
__device__ __forceinline__ void ldsm_x4_t(unsigned* r, unsigned a) {
    asm volatile("ldmatrix.sync.aligned.m8n8.x4.trans.shared.b16 {%0,%1,%2,%3}, [%4];"
                 : "=r"(r[0]), "=r"(r[1]), "=r"(r[2]), "=r"(r[3]) : "r"(a));
}

__device__ __forceinline__ void cp_async16(void* smem_dst, const void* gmem_src) {
    unsigned s = (unsigned)__cvta_generic_to_shared(smem_dst);
    asm volatile("cp.async.cg.shared.global [%0], [%1], 16;" :: "r"(s), "l"(gmem_src));
}

// MUFU exp2
__device__ __forceinline__ float ex2_mufu(float x) {
    float y;
    asm("ex2.approx.ftz.f32 %0, %1;" : "=f"(y) : "f"(x));
    return y;
}

// FMA-pipe exp2: minimax on f in [-0.5, 0.5], ~1e-7 rel err.
__device__ __forceinline__ float exp2_poly(float x) {
    x = fmaxf(x, -120.f);
    float t = x + 12582912.f;
    float i = t - 12582912.f;
    float f = x - i;
    float p = 1.535336188319500e-4f;
    p = fmaf(p, f, 1.339887440266574e-3f);
    p = fmaf(p, f, 9.618437357674640e-3f);
    p = fmaf(p, f, 5.550332471162809e-2f);
    p = fmaf(p, f, 2.402264791363012e-1f);
    p = fmaf(p, f, 6.931472028550421e-1f);
    p = fmaf(p, f, 1.0f);
    int ii = (int)i;
    return p * __int_as_float((ii + 127) << 23);
}

// exact 2^d for integer d <= 0 (0 if underflow)
__device__ __forceinline__ float pow2i(int d) {
    int b = 127 + d;
    return (b > 0) ? __int_as_float(b << 23) : 0.f;
}

// ---------------------------------------------------------------------------
// Prep 1: convert H to fp16 [M][K]
// ---------------------------------------------------------------------------
__global__ void prep_H_half(const float4* __restrict__ H, __half2* __restrict__ Hh)
{
    const int n4 = T_SEQ * HID / 4;
    int stride = gridDim.x * blockDim.x;
    for (int i = blockIdx.x * blockDim.x + threadIdx.x; i < n4; i += stride) {
        float4 v = H[i];
        Hh[i * 2]     = __floats2half2_rn(v.x, v.y);
        Hh[i * 2 + 1] = __floats2half2_rn(v.z, v.w);
    }
}

// ---------------------------------------------------------------------------
// Prep 2: transpose+convert Wq and Wo (4096x4096) -> fp16 [N][K] via blockIdx.z
// ---------------------------------------------------------------------------
__global__ void prep_transpose_QO(const float* __restrict__ Wq,
                                  const float* __restrict__ Wo,
                                  __half* __restrict__ Wh,
                                  __half* __restrict__ Woh)
{
    __shared__ float tile[32][33];
    const float* W = blockIdx.z ? Wo : Wq;
    __half* dst    = blockIdx.z ? Woh : Wh;
    const int N = 4096, K = 4096;
    int x = blockIdx.x * 32 + threadIdx.x;
#pragma unroll
    for (int j = 0; j < 4; j++) {
        int y = blockIdx.y * 32 + threadIdx.y + j * 8;
        tile[threadIdx.y + j * 8][threadIdx.x] = W[(size_t)y * N + x];
    }
    __syncthreads();
    int k = blockIdx.y * 32 + threadIdx.x;
#pragma unroll
    for (int j = 0; j < 4; j++) {
        int n = blockIdx.x * 32 + threadIdx.y + j * 8;
        dst[(size_t)n * K + k] = __float2half_rn(tile[threadIdx.x][threadIdx.y + j * 8]);
    }
}

// ---------------------------------------------------------------------------
// Prep 3: transpose+convert Wk (rows 4096..) / Wv (rows 5120..) via blockIdx.z
// ---------------------------------------------------------------------------
__global__ void prep_transpose_KV(const float* __restrict__ Wk,
                                  const float* __restrict__ Wv,
                                  __half* __restrict__ Wh)
{
    __shared__ float tile[32][33];
    const float* W = blockIdx.z ? Wv : Wk;
    const int rowOff = blockIdx.z ? V_OFF : K_OFF;
    const int N = 1024, K = 4096;
    int x = blockIdx.x * 32 + threadIdx.x;
#pragma unroll
    for (int j = 0; j < 4; j++) {
        int y = blockIdx.y * 32 + threadIdx.y + j * 8;
        tile[threadIdx.y + j * 8][threadIdx.x] = W[(size_t)y * N + x];
    }
    __syncthreads();
    int k = blockIdx.y * 32 + threadIdx.x;
#pragma unroll
    for (int j = 0; j < 4; j++) {
        int n = blockIdx.x * 32 + threadIdx.y + j * 8;
        Wh[(size_t)(rowOff + n) * K + k] = __float2half_rn(tile[threadIdx.x][threadIdx.y + j * 8]);
    }
}

// ---------------------------------------------------------------------------
// FP16 tensor GEMM (R13 exact): C[M,N] = A[M,K] @ Bt[N,K]^T, fp32 accumulate.
// CTA tile 128x128x64, 256 threads, 2 CTAs/SM, 3-stage cp.async, ldmatrix both.
// ---------------------------------------------------------------------------
#define GEMMH_SMEM (3 * 2 * 128 * 72 * 2)

__global__ __launch_bounds__(256, 2) void h16gemm(const __half* __restrict__ A,
                                                  const __half* __restrict__ Bt,
                                                  float* __restrict__ C,
                                                  int M, int N, int K)
{
    extern __shared__ __half smh[];
    const int tid  = threadIdx.x;
    const int wid  = tid >> 5;
    const int lane = tid & 31;
    const int g    = lane >> 2;
    const int tg   = lane & 3;
    const int wm   = (wid >> 2) * 64;
    const int wn   = (wid & 3) * 32;
    const int bm   = blockIdx.y * 128;
    const int bn   = blockIdx.x * 128;

    const __half* Ab = A  + (size_t)bm * K;
    const __half* Bb = Bt + (size_t)bn * K;

    const unsigned lane_off = ((lane & 15) * 144) + ((lane >> 4) * 16);

    float acc[4][4][4];
#pragma unroll
    for (int mt = 0; mt < 4; mt++)
#pragma unroll
        for (int nt = 0; nt < 4; nt++)
#pragma unroll
            for (int i = 0; i < 4; i++) acc[mt][nt][i] = 0.f;

    const int ntiles = K >> 6;

    auto issue = [&](int t) {
        __half* As_ = smh + (t % 3) * 18432;
        __half* Bs_ = As_ + 9216;
        const int kt = t << 6;
#pragma unroll
        for (int i_ = 0; i_ < 4; i_++) {
            int ch = tid + i_ * 256;
            int r = ch >> 3, c = ch & 7;
            cp_async16(As_ + r * 72 + c * 8, Ab + (size_t)r * K + kt + c * 8);
            cp_async16(Bs_ + r * 72 + c * 8, Bb + (size_t)r * K + kt + c * 8);
        }
        asm volatile("cp.async.commit_group;");
    };

    issue(0);
    issue(1);

    for (int t = 0; t < ntiles; t++) {
        if (t == ntiles - 1) asm volatile("cp.async.wait_group 0;");
        else                 asm volatile("cp.async.wait_group 1;");
        __syncthreads();
        if (t + 2 < ntiles) issue(t + 2);

        const __half* As_ = smh + (t % 3) * 18432;
        const __half* Bs_ = As_ + 9216;
        const unsigned a_base = (unsigned)__cvta_generic_to_shared(As_) + lane_off;
        const unsigned b_base = (unsigned)__cvta_generic_to_shared(Bs_) + lane_off;

#pragma unroll
        for (int kk = 0; kk < 64; kk += 16) {
            unsigned af[4][4], bq[2][4];
#pragma unroll
            for (int mt = 0; mt < 4; mt++)
                ldsm_x4(af[mt], a_base + (wm + mt * 16) * 144 + kk * 2);
#pragma unroll
            for (int np = 0; np < 2; np++)
                ldsm_x4(bq[np], b_base + (wn + np * 16) * 144 + kk * 2);
#pragma unroll
            for (int mt = 0; mt < 4; mt++)
#pragma unroll
                for (int nt = 0; nt < 4; nt++) {
                    unsigned b[2] = { bq[nt >> 1][nt & 1], bq[nt >> 1][(nt & 1) + 2] };
                    mma_f16(acc[mt][nt], af[mt], b);
                }
        }
    }

#pragma unroll
    for (int mt = 0; mt < 4; mt++) {
#pragma unroll
        for (int nt = 0; nt < 4; nt++) {
            int row = bm + wm + mt * 16 + g;
            int col = bn + wn + nt * 8 + tg * 2;
            *(float2*)&C[(size_t)row * N + col]       = make_float2(acc[mt][nt][0], acc[mt][nt][1]);
            *(float2*)&C[(size_t)(row + 8) * N + col] = make_float2(acc[mt][nt][2], acc[mt][nt][3]);
        }
    }
}

// ---------------------------------------------------------------------------
// RoPE: reads fused qkv (fp32); writes Q (scaled) / K / V as fp16.
// ---------------------------------------------------------------------------
__global__ void rope_split_kernel(const float* __restrict__ cosp,
                                  const float* __restrict__ sinp)
{
    const int t = blockIdx.x;
    const float* rowp = &g_qkv[(size_t)t * QKV_N];
    for (int p = threadIdx.x; p < (HQ + HKV) * 64; p += blockDim.x) {
        int h = p >> 6;
        int d = p & 63;
        float c = cosp[t * DH + d];
        float s = sinp[t * DH + d];
        if (h < HQ) {
            const float* base = rowp + h * DH;
            float x1 = base[d], x2 = base[d + 64];
            __half* qb = &g_qh[(size_t)t * (HQ * DH) + h * DH];
            qb[d]      = __float2half_rn((x1 * c - x2 * s) * QSCALE_F);
            qb[d + 64] = __float2half_rn((x2 * c + x1 * s) * QSCALE_F);
        } else {
            const float* base = rowp + K_OFF + (h - HQ) * DH;
            float x1 = base[d], x2 = base[d + 64];
            __half* kb = &g_kh[(size_t)t * (HKV * DH) + (h - HQ) * DH];
            kb[d]      = __float2half_rn(x1 * c - x2 * s);
            kb[d + 64] = __float2half_rn(x2 * c + x1 * s);
        }
    }
    for (int i = threadIdx.x; i < HKV * DH; i += blockDim.x) {
        g_vh[(size_t)t * (HKV * DH) + i] = __float2half_rn(rowp[V_OFF + i]);
    }
}

// ---------------------------------------------------------------------------
// Flash attention, all-fp16 MMA: Q@K and P@V both m16n8k16, fp32 accum.
// Integer-quantized running row max -> P in (0,1], safe in fp16.
// 64 queries x 1 head, 128 threads, 3 CTAs/SM.
// smem: Ksh fp16[64][136] | Vsh fp16[64][136] | Ps fp16[64][72]  = 44,032 B
// ---------------------------------------------------------------------------
#define ATT_SMEM_BYTES (17408 + 17408 + 9216)

__global__ __launch_bounds__(128, 3) void attn_mma_kernel()
{
    extern __shared__ char smb[];
    __half* Ksh = (__half*)smb;                  // [64][136]
    __half* Vsh = (__half*)(smb + 17408);        // [64][136]
    __half* Ps  = (__half*)(smb + 34816);        // [64][72]

    const int h    = blockIdx.y;
    const int kvh  = h / GROUPS;
    const int qi   = gridDim.x - 1 - blockIdx.x;   // long CTAs first
    const int q0   = qi * 64;
    const int tid  = threadIdx.x;
    const int w    = tid >> 5;
    const int lane = tid & 31;
    const int g    = lane >> 2;
    const int tg   = lane & 3;
    const int wrow = w * 16;

    // A/B-frag ldmatrix lane offsets (bytes)
    const unsigned h_lane_off = ((lane & 15) * 272) + ((lane >> 4) * 16);   // stride 136 fp16
    const unsigned p_lane_off = ((lane & 15) * 144) + ((lane >> 4) * 16);   // stride 72 fp16
    // V trans b-frag: matrix mi = lane>>3 -> (k-half mi&1, n-block mi>>1); row = lane&7
    const unsigned v_lane_off = ((((lane >> 3) & 1) * 8 + (lane & 7)) * 272)
                                + (((lane >> 3) >> 1) * 16);
    const unsigned ks_smem = (unsigned)__cvta_generic_to_shared(Ksh);
    const unsigned vs_smem = (unsigned)__cvta_generic_to_shared(Vsh);
    const unsigned ps_base = (unsigned)__cvta_generic_to_shared(Ps) + p_lane_off
                             + (unsigned)(wrow * 144);

    // ---- stage Q tile (fp16) through Ksh; move to fragments
    for (int idx = tid; idx < 64 * 16; idx += 128) {
        int r = idx >> 4, c8 = (idx & 15) << 3;
        *(float4*)&Ksh[r * 136 + c8] =
            *(const float4*)&g_qh[(size_t)(q0 + r) * (HQ * DH) + h * DH + c8];
    }
    __syncthreads();
    unsigned qf[8][4];
    {
        const unsigned q_base = ks_smem + h_lane_off + (unsigned)(wrow * 272);
#pragma unroll
        for (int kk = 0; kk < 8; kk++)
            ldsm_x4(qf[kk], q_base + kk * 32);
    }
    __syncthreads();

    float acc_o[16][4];
#pragma unroll
    for (int nt = 0; nt < 16; nt++)
#pragma unroll
        for (int i = 0; i < 4; i++) acc_o[nt][i] = 0.f;
    float l0 = 0.f, l1 = 0.f;
    int   mi0 = -10000, mi1 = -10000;    // integer running max (log2 domain)

    for (int k0 = 0; k0 <= q0; k0 += 64) {
        // load K and V tiles (fp16)
        for (int idx = tid; idx < 64 * 32; idx += 128) {
            int sel = idx >> 10;
            int j = idx & 1023;
            int r = j >> 4, c8 = (j & 15) << 3;
            size_t go = (size_t)(k0 + r) * (HKV * DH) + kvh * DH + c8;
            if (sel == 0) *(float4*)&Ksh[r * 136 + c8] = *(const float4*)&g_kh[go];
            else          *(float4*)&Vsh[r * 136 + c8] = *(const float4*)&g_vh[go];
        }
        __syncthreads();

        // ---- S2 = Q @ K^T  (fp16 mma)
        float acc_s[8][4];
#pragma unroll
        for (int nt = 0; nt < 8; nt++)
#pragma unroll
            for (int i = 0; i < 4; i++) acc_s[nt][i] = 0.f;
        const unsigned kb_base = ks_smem + h_lane_off;
#pragma unroll
        for (int kk = 0; kk < 8; kk++) {
#pragma unroll
            for (int ntp = 0; ntp < 4; ntp++) {
                unsigned kq[4];
                ldsm_x4(kq, kb_base + (unsigned)(ntp * 16 * 272) + kk * 32);
                unsigned b0[2] = { kq[0], kq[2] };
                unsigned b1[2] = { kq[1], kq[3] };
                mma_f16(acc_s[2 * ntp],     qf[kk], b0);
                mma_f16(acc_s[2 * ntp + 1], qf[kk], b1);
            }
        }

        // ---- causal mask (diag tile) + integer running max
        const bool diag = (k0 == q0);
        const int r0 = q0 + wrow + g, r1 = r0 + 8;
        float mx0 = -1e30f, mx1 = -1e30f;
#pragma unroll
        for (int nt = 0; nt < 8; nt++) {
            if (diag) {
                int col0 = k0 + nt * 8 + tg * 2;
                if (col0     > r0) acc_s[nt][0] = -1e30f;
                if (col0 + 1 > r0) acc_s[nt][1] = -1e30f;
                if (col0     > r1) acc_s[nt][2] = -1e30f;
                if (col0 + 1 > r1) acc_s[nt][3] = -1e30f;
            }
            mx0 = fmaxf(mx0, fmaxf(acc_s[nt][0], acc_s[nt][1]));
            mx1 = fmaxf(mx1, fmaxf(acc_s[nt][2], acc_s[nt][3]));
        }
        mx0 = fmaxf(mx0, __shfl_xor_sync(0xffffffffu, mx0, 1));
        mx0 = fmaxf(mx0, __shfl_xor_sync(0xffffffffu, mx0, 2));
        mx1 = fmaxf(mx1, __shfl_xor_sync(0xffffffffu, mx1, 1));
        mx1 = fmaxf(mx1, __shfl_xor_sync(0xffffffffu, mx1, 2));
        int n0 = max(mi0, (int)ceilf(mx0));
        int n1 = max(mi1, (int)ceilf(mx1));
        float sc0 = pow2i(mi0 - n0);
        float sc1 = pow2i(mi1 - n1);
        mi0 = n0; mi1 = n1;
        l0 *= sc0; l1 *= sc1;
#pragma unroll
        for (int nt = 0; nt < 16; nt++) {
            acc_o[nt][0] *= sc0; acc_o[nt][1] *= sc0;
            acc_o[nt][2] *= sc1; acc_o[nt][3] *= sc1;
        }
        const float fm0 = (float)n0, fm1 = (float)n1;

        // ---- p = 2^(s - m) in (0,1]; 25% poly / 75% MUFU; store fp16
#pragma unroll
        for (int nt = 0; nt < 8; nt++) {
            float x0 = acc_s[nt][0] - fm0;
            float x1 = acc_s[nt][1] - fm0;
            float x2 = acc_s[nt][2] - fm1;
            float x3 = acc_s[nt][3] - fm1;
            float p0, p1, p2, p3;
            if (nt < 2) {
                p0 = exp2_poly(x0); p1 = exp2_poly(x1);
                p2 = exp2_poly(x2); p3 = exp2_poly(x3);
            } else {
                p0 = ex2_mufu(x0); p1 = ex2_mufu(x1);
                p2 = ex2_mufu(x2); p3 = ex2_mufu(x3);
            }
            l0 += p0 + p1;
            l1 += p2 + p3;
            *(__half2*)&Ps[(wrow + g) * 72 + nt * 8 + tg * 2]     = __floats2half2_rn(p0, p1);
            *(__half2*)&Ps[(wrow + g + 8) * 72 + nt * 8 + tg * 2] = __floats2half2_rn(p2, p3);
        }
        __syncwarp();   // Ps rows are warp-private

        // ---- O += P @ V  (fp16 mma; V b-frags via ldmatrix.trans)
#pragma unroll
        for (int kk = 0; kk < 4; kk++) {
            unsigned a[4];
            ldsm_x4(a, ps_base + kk * 32);
            const unsigned vkk = vs_smem + v_lane_off + (unsigned)(kk * 16 * 272);
#pragma unroll
            for (int np = 0; np < 8; np++) {
                unsigned kq[4];
                ldsm_x4_t(kq, vkk + np * 32);
                unsigned b0[2] = { kq[0], kq[1] };
                unsigned b1[2] = { kq[2], kq[3] };
                mma_f16(acc_o[np * 2],     a, b0);
                mma_f16(acc_o[np * 2 + 1], a, b1);
            }
        }
        __syncthreads();
    }

    l0 += __shfl_xor_sync(0xffffffffu, l0, 1);
    l0 += __shfl_xor_sync(0xffffffffu, l0, 2);
    l1 += __shfl_xor_sync(0xffffffffu, l1, 1);
    l1 += __shfl_xor_sync(0xffffffffu, l1, 2);
    const float inv0 = 1.f / l0;
    const float inv1 = 1.f / l1;

    const int row0 = q0 + wrow + g, row1 = row0 + 8;
#pragma unroll
    for (int nt = 0; nt < 16; nt++) {
        int col = h * DH + nt * 8 + tg * 2;
        *(__half2*)&g_attnh[(size_t)row0 * (HQ * DH) + col] =
            __floats2half2_rn(acc_o[nt][0] * inv0, acc_o[nt][1] * inv0);
        *(__half2*)&g_attnh[(size_t)row1 * (HQ * DH) + col] =
            __floats2half2_rn(acc_o[nt][2] * inv1, acc_o[nt][3] * inv1);
    }
}

// ---------------------------------------------------------------------------
// Launch pipeline (7 launches). Inputs:
// 0 H | 1 pos | 2 cos | 3 sin | 4 Wq | 5 Wk | 6 Wv | 7 Wo
// ---------------------------------------------------------------------------
extern "C" void kernel_launch(void* const* d_in, const int* in_sizes, int n_in,
                              void* d_out, int out_size)
{
    const float* H    = (const float*)d_in[0];
    const float* cosp = (const float*)d_in[2];
    const float* sinp = (const float*)d_in[3];
    const float* Wq   = (const float*)d_in[4];
    const float* Wk   = (const float*)d_in[5];
    const float* Wv   = (const float*)d_in[6];
    const float* Wo   = (const float*)d_in[7];
    float* out = (float*)d_out;

    float *qkv;
    __half *attnh, *Hh, *Wh, *Woh;
    cudaGetSymbolAddress((void**)&qkv,   g_qkv);
    cudaGetSymbolAddress((void**)&attnh, g_attnh);
    cudaGetSymbolAddress((void**)&Hh,    g_Hh);
    cudaGetSymbolAddress((void**)&Wh,    g_Wh);
    cudaGetSymbolAddress((void**)&Woh,   g_Woh);

    cudaFuncSetAttribute(h16gemm, cudaFuncAttributeMaxDynamicSharedMemorySize, GEMMH_SMEM);
    cudaFuncSetAttribute(attn_mma_kernel, cudaFuncAttributeMaxDynamicSharedMemorySize, ATT_SMEM_BYTES);

    // Prep (3 launches)
    prep_H_half<<<512, 256>>>((const float4*)H, (__half2*)Hh);
    prep_transpose_QO<<<dim3(128, 128, 2), dim3(32, 8)>>>(Wq, Wo, Wh, Woh);
    prep_transpose_KV<<<dim3(32, 128, 2), dim3(32, 8)>>>(Wk, Wv, Wh);

    // Fused QKV projection, fp16 tensor cores (launch 4)
    h16gemm<<<dim3(QKV_N / 128, T_SEQ / 128), 256, GEMMH_SMEM>>>(
        Hh, Wh, qkv, T_SEQ, QKV_N, HID);

    // RoPE -> fp16 Q/K/V (launch 5)
    rope_split_kernel<<<T_SEQ, 256>>>(cosp, sinp);

    // Attention: all-fp16 MMA, 3 CTAs/SM (launch 6)
    attn_mma_kernel<<<dim3(T_SEQ / 64, HQ), 128, ATT_SMEM_BYTES>>>();

    // Output projection, fp16 tensor cores (launch 7)
    h16gemm<<<dim3(HID / 128, T_SEQ / 128), 256, GEMMH_SMEM>>>(
        attnh, Woh, out, T_SEQ, HID, HQ * DH);
}

// round 16
// speedup vs baseline: 2.5550x; 1.0354x over previous
#include <cuda_runtime.h>
#include <cuda_bf16.h>
#include <cuda_fp16.h>
#include <math.h>

#define T_SEQ 2048
#define HID   4096
#define HQ    32
#define HKV   8
#define DH    128
#define GROUPS (HQ / HKV)
#define QKV_N 6144                      // 4096 q | 1024 k | 1024 v
#define K_OFF 4096
#define V_OFF 5120

// q pre-scale: 1/sqrt(128) * log2(e)  (softmax runs in exp2 domain)
#define QSCALE_F ((float)(0.08838834764831845 * 1.4426950408889634))

// ---------------- device scratch (no allocs allowed) ----------------
__device__ float  g_qkv[T_SEQ * QKV_N];       // 50 MB  fused q|k|v (fp32, GEMM out)
__device__ __half g_qh [T_SEQ * HQ * DH];     // 16 MB  roped+scaled Q (fp16)
__device__ __half g_kh [T_SEQ * HKV * DH];    // 4 MB   roped K (fp16)
__device__ __half g_vh [T_SEQ * HKV * DH];    // 4 MB   V (fp16)
__device__ __half g_attnh[T_SEQ * HQ * DH];   // 16 MB  attention out (fp16)
__device__ __half g_Hh [T_SEQ * HID];         // 16 MB  fp16 H [M][K]
__device__ __half g_Wh [QKV_N * HID];         // 48 MB  fp16 [Wq|Wk|Wv] transposed [N][K]
__device__ __half g_Woh[HID * HQ * DH];       // 32 MB  fp16 Wo transposed [N][K]

__device__ __forceinline__ void mma_f16(float* d, const unsigned* a, const unsigned* b) {
    asm volatile(
        "mma.sync.aligned.m16n8k16.row.col.f32.f16.f16.f32 "
        "{%0,%1,%2,%3}, {%4,%5,%6,%7}, {%8,%9}, {%0,%1,%2,%3};"
        : "+f"(d[0]), "+f"(d[1]), "+f"(d[2]), "+f"(d[3])
        : "r"(a[0]), "r"(a[1]), "r"(a[2]), "r"(a[3]), "r"(b[0]), "r"(b[1]));
}

// ldmatrix x4: lane L supplies the 16B row address of matrix (L>>3).
__device__ __forceinline__ void ldsm_x4(unsigned* r, unsigned a) {
    asm volatile("ldmatrix.sync.aligned.m8n8.x4.shared.b16 {%0,%1,%2,%3}, [%4];"
                 : "=r"(r[0]), "=r"(r[1]), "=r"(r[2]), "=r"(r[3]) : "r"(a));
}
// transposed variant (k-major B tiles) -> fp16 mma b-frag distribution.
__device__ __forceinline__ void ldsm_x4_t(unsigned* r, unsigned a) {
    asm volatile("ldmatrix.sync.aligned.m8n8.x4.trans.shared.b16 {%0,%1,%2,%3}, [%4];"
                 : "=r"(r[0]), "=r"(r[1]), "=r"(r[2]), "=r"(r[3]) : "r"(a));
}

__device__ __forceinline__ void cp_async16(void* smem_dst, const void* gmem_src) {
    unsigned s = (unsigned)__cvta_generic_to_shared(smem_dst);
    asm volatile("cp.async.cg.shared.global [%0], [%1], 16;" :: "r"(s), "l"(gmem_src));
}

// MUFU exp2
__device__ __forceinline__ float ex2_mufu(float x) {
    float y;
    asm("ex2.approx.ftz.f32 %0, %1;" : "=f"(y) : "f"(x));
    return y;
}

// FMA-pipe exp2: minimax on f in [-0.5, 0.5], ~1e-7 rel err.
__device__ __forceinline__ float exp2_poly(float x) {
    x = fmaxf(x, -120.f);
    float t = x + 12582912.f;
    float i = t - 12582912.f;
    float f = x - i;
    float p = 1.535336188319500e-4f;
    p = fmaf(p, f, 1.339887440266574e-3f);
    p = fmaf(p, f, 9.618437357674640e-3f);
    p = fmaf(p, f, 5.550332471162809e-2f);
    p = fmaf(p, f, 2.402264791363012e-1f);
    p = fmaf(p, f, 6.931472028550421e-1f);
    p = fmaf(p, f, 1.0f);
    int ii = (int)i;
    return p * __int_as_float((ii + 127) << 23);
}

// exact 2^d for integer d <= 0 (0 if underflow)
__device__ __forceinline__ float pow2i(int d) {
    int b = 127 + d;
    return (b > 0) ? __int_as_float(b << 23) : 0.f;
}

// ---------------------------------------------------------------------------
// Prep 1: convert H to fp16 [M][K]
// ---------------------------------------------------------------------------
__global__ void prep_H_half(const float4* __restrict__ H, __half2* __restrict__ Hh)
{
    const int n4 = T_SEQ * HID / 4;
    int stride = gridDim.x * blockDim.x;
    for (int i = blockIdx.x * blockDim.x + threadIdx.x; i < n4; i += stride) {
        float4 v = H[i];
        Hh[i * 2]     = __floats2half2_rn(v.x, v.y);
        Hh[i * 2 + 1] = __floats2half2_rn(v.z, v.w);
    }
}

// ---------------------------------------------------------------------------
// Prep 2: transpose+convert Wq and Wo (4096x4096) -> fp16 [N][K] via blockIdx.z
// ---------------------------------------------------------------------------
__global__ void prep_transpose_QO(const float* __restrict__ Wq,
                                  const float* __restrict__ Wo,
                                  __half* __restrict__ Wh,
                                  __half* __restrict__ Woh)
{
    __shared__ float tile[32][33];
    const float* W = blockIdx.z ? Wo : Wq;
    __half* dst    = blockIdx.z ? Woh : Wh;
    const int N = 4096, K = 4096;
    int x = blockIdx.x * 32 + threadIdx.x;
#pragma unroll
    for (int j = 0; j < 4; j++) {
        int y = blockIdx.y * 32 + threadIdx.y + j * 8;
        tile[threadIdx.y + j * 8][threadIdx.x] = W[(size_t)y * N + x];
    }
    __syncthreads();
    int k = blockIdx.y * 32 + threadIdx.x;
#pragma unroll
    for (int j = 0; j < 4; j++) {
        int n = blockIdx.x * 32 + threadIdx.y + j * 8;
        dst[(size_t)n * K + k] = __float2half_rn(tile[threadIdx.x][threadIdx.y + j * 8]);
    }
}

// ---------------------------------------------------------------------------
// Prep 3: transpose+convert Wk (rows 4096..) / Wv (rows 5120..) via blockIdx.z
// ---------------------------------------------------------------------------
__global__ void prep_transpose_KV(const float* __restrict__ Wk,
                                  const float* __restrict__ Wv,
                                  __half* __restrict__ Wh)
{
    __shared__ float tile[32][33];
    const float* W = blockIdx.z ? Wv : Wk;
    const int rowOff = blockIdx.z ? V_OFF : K_OFF;
    const int N = 1024, K = 4096;
    int x = blockIdx.x * 32 + threadIdx.x;
#pragma unroll
    for (int j = 0; j < 4; j++) {
        int y = blockIdx.y * 32 + threadIdx.y + j * 8;
        tile[threadIdx.y + j * 8][threadIdx.x] = W[(size_t)y * N + x];
    }
    __syncthreads();
    int k = blockIdx.y * 32 + threadIdx.x;
#pragma unroll
    for (int j = 0; j < 4; j++) {
        int n = blockIdx.x * 32 + threadIdx.y + j * 8;
        Wh[(size_t)(rowOff + n) * K + k] = __float2half_rn(tile[threadIdx.x][threadIdx.y + j * 8]);
    }
}

// ---------------------------------------------------------------------------
// FP16 tensor GEMM (R13 exact): C[M,N] = A[M,K] @ Bt[N,K]^T, fp32 accumulate.
// CTA tile 128x128x64, 256 threads, 2 CTAs/SM, 3-stage cp.async, ldmatrix both.
// ---------------------------------------------------------------------------
#define GEMMH_SMEM (3 * 2 * 128 * 72 * 2)

__global__ __launch_bounds__(256, 2) void h16gemm(const __half* __restrict__ A,
                                                  const __half* __restrict__ Bt,
                                                  float* __restrict__ C,
                                                  int M, int N, int K)
{
    extern __shared__ __half smh[];
    const int tid  = threadIdx.x;
    const int wid  = tid >> 5;
    const int lane = tid & 31;
    const int g    = lane >> 2;
    const int tg   = lane & 3;
    const int wm   = (wid >> 2) * 64;
    const int wn   = (wid & 3) * 32;
    const int bm   = blockIdx.y * 128;
    const int bn   = blockIdx.x * 128;

    const __half* Ab = A  + (size_t)bm * K;
    const __half* Bb = Bt + (size_t)bn * K;

    const unsigned lane_off = ((lane & 15) * 144) + ((lane >> 4) * 16);

    float acc[4][4][4];
#pragma unroll
    for (int mt = 0; mt < 4; mt++)
#pragma unroll
        for (int nt = 0; nt < 4; nt++)
#pragma unroll
            for (int i = 0; i < 4; i++) acc[mt][nt][i] = 0.f;

    const int ntiles = K >> 6;

    auto issue = [&](int t) {
        __half* As_ = smh + (t % 3) * 18432;
        __half* Bs_ = As_ + 9216;
        const int kt = t << 6;
#pragma unroll
        for (int i_ = 0; i_ < 4; i_++) {
            int ch = tid + i_ * 256;
            int r = ch >> 3, c = ch & 7;
            cp_async16(As_ + r * 72 + c * 8, Ab + (size_t)r * K + kt + c * 8);
            cp_async16(Bs_ + r * 72 + c * 8, Bb + (size_t)r * K + kt + c * 8);
        }
        asm volatile("cp.async.commit_group;");
    };

    issue(0);
    issue(1);

    for (int t = 0; t < ntiles; t++) {
        if (t == ntiles - 1) asm volatile("cp.async.wait_group 0;");
        else                 asm volatile("cp.async.wait_group 1;");
        __syncthreads();
        if (t + 2 < ntiles) issue(t + 2);

        const __half* As_ = smh + (t % 3) * 18432;
        const __half* Bs_ = As_ + 9216;
        const unsigned a_base = (unsigned)__cvta_generic_to_shared(As_) + lane_off;
        const unsigned b_base = (unsigned)__cvta_generic_to_shared(Bs_) + lane_off;

#pragma unroll
        for (int kk = 0; kk < 64; kk += 16) {
            unsigned af[4][4], bq[2][4];
#pragma unroll
            for (int mt = 0; mt < 4; mt++)
                ldsm_x4(af[mt], a_base + (wm + mt * 16) * 144 + kk * 2);
#pragma unroll
            for (int np = 0; np < 2; np++)
                ldsm_x4(bq[np], b_base + (wn + np * 16) * 144 + kk * 2);
#pragma unroll
            for (int mt = 0; mt < 4; mt++)
#pragma unroll
                for (int nt = 0; nt < 4; nt++) {
                    unsigned b[2] = { bq[nt >> 1][nt & 1], bq[nt >> 1][(nt & 1) + 2] };
                    mma_f16(acc[mt][nt], af[mt], b);
                }
        }
    }

#pragma unroll
    for (int mt = 0; mt < 4; mt++) {
#pragma unroll
        for (int nt = 0; nt < 4; nt++) {
            int row = bm + wm + mt * 16 + g;
            int col = bn + wn + nt * 8 + tg * 2;
            *(float2*)&C[(size_t)row * N + col]       = make_float2(acc[mt][nt][0], acc[mt][nt][1]);
            *(float2*)&C[(size_t)(row + 8) * N + col] = make_float2(acc[mt][nt][2], acc[mt][nt][3]);
        }
    }
}

// ---------------------------------------------------------------------------
// RoPE: reads fused qkv (fp32); writes Q (scaled) / K / V as fp16.
// ---------------------------------------------------------------------------
__global__ void rope_split_kernel(const float* __restrict__ cosp,
                                  const float* __restrict__ sinp)
{
    const int t = blockIdx.x;
    const float* rowp = &g_qkv[(size_t)t * QKV_N];
    for (int p = threadIdx.x; p < (HQ + HKV) * 64; p += blockDim.x) {
        int h = p >> 6;
        int d = p & 63;
        float c = cosp[t * DH + d];
        float s = sinp[t * DH + d];
        if (h < HQ) {
            const float* base = rowp + h * DH;
            float x1 = base[d], x2 = base[d + 64];
            __half* qb = &g_qh[(size_t)t * (HQ * DH) + h * DH];
            qb[d]      = __float2half_rn((x1 * c - x2 * s) * QSCALE_F);
            qb[d + 64] = __float2half_rn((x2 * c + x1 * s) * QSCALE_F);
        } else {
            const float* base = rowp + K_OFF + (h - HQ) * DH;
            float x1 = base[d], x2 = base[d + 64];
            __half* kb = &g_kh[(size_t)t * (HKV * DH) + (h - HQ) * DH];
            kb[d]      = __float2half_rn(x1 * c - x2 * s);
            kb[d + 64] = __float2half_rn(x2 * c + x1 * s);
        }
    }
    for (int i = threadIdx.x; i < HKV * DH; i += blockDim.x) {
        g_vh[(size_t)t * (HKV * DH) + i] = __float2half_rn(rowp[V_OFF + i]);
    }
}

// ---------------------------------------------------------------------------
// Flash attention, all-fp16 MMA + cp.async-pipelined K/V loads.
// K(t+1) issued after S2 (hidden behind softmax+P@V); V(t+1) issued at
// iteration end (hidden behind next S2+softmax). Single K/V buffer.
// FIFO ledger keeps pending ⊆ {K(t),V(t)} or {V(t),K(t+1)} -> wait_group 1
// retires exactly the needed tile; last-iter V wait uses wait_group 0.
// 64 queries x 1 head, 128 threads, 3 CTAs/SM. smem 44,032 B.
// ---------------------------------------------------------------------------
#define ATT_SMEM_BYTES (17408 + 17408 + 9216)

__global__ __launch_bounds__(128, 3) void attn_mma_kernel()
{
    extern __shared__ char smb[];
    __half* Ksh = (__half*)smb;                  // [64][136]
    __half* Vsh = (__half*)(smb + 17408);        // [64][136]
    __half* Ps  = (__half*)(smb + 34816);        // [64][72]

    const int h    = blockIdx.y;
    const int kvh  = h / GROUPS;
    const int qi   = gridDim.x - 1 - blockIdx.x;   // long CTAs first
    const int q0   = qi * 64;
    const int tid  = threadIdx.x;
    const int w    = tid >> 5;
    const int lane = tid & 31;
    const int g    = lane >> 2;
    const int tg   = lane & 3;
    const int wrow = w * 16;

    const unsigned h_lane_off = ((lane & 15) * 272) + ((lane >> 4) * 16);   // stride 136 fp16
    const unsigned p_lane_off = ((lane & 15) * 144) + ((lane >> 4) * 16);   // stride 72 fp16
    const unsigned v_lane_off = ((((lane >> 3) & 1) * 8 + (lane & 7)) * 272)
                                + (((lane >> 3) >> 1) * 16);
    const unsigned ks_smem = (unsigned)__cvta_generic_to_shared(Ksh);
    const unsigned vs_smem = (unsigned)__cvta_generic_to_shared(Vsh);
    const unsigned ps_base = (unsigned)__cvta_generic_to_shared(Ps) + p_lane_off
                             + (unsigned)(wrow * 144);

    // ---- stage Q tile (fp16) through Ksh; move to fragments
    for (int idx = tid; idx < 64 * 16; idx += 128) {
        int r = idx >> 4, c8 = (idx & 15) << 3;
        *(float4*)&Ksh[r * 136 + c8] =
            *(const float4*)&g_qh[(size_t)(q0 + r) * (HQ * DH) + h * DH + c8];
    }
    __syncthreads();
    unsigned qf[8][4];
    {
        const unsigned q_base = ks_smem + h_lane_off + (unsigned)(wrow * 272);
#pragma unroll
        for (int kk = 0; kk < 8; kk++)
            ldsm_x4(qf[kk], q_base + kk * 32);
    }
    __syncthreads();   // Q frags read before K(0) cp.async overwrites Ksh

    // per-thread cp.async chunk coords (8 chunks of 8 fp16 each per tile)
    auto issueK = [&](int t) {
        const int k0 = t * 64;
#pragma unroll
        for (int i = 0; i < 8; i++) {
            int ch = tid + i * 128;          // 0..1023
            int r = ch >> 4, c8 = (ch & 15) << 3;
            cp_async16(Ksh + r * 136 + c8,
                       &g_kh[(size_t)(k0 + r) * (HKV * DH) + kvh * DH + c8]);
        }
        asm volatile("cp.async.commit_group;");
    };
    auto issueV = [&](int t) {
        const int k0 = t * 64;
#pragma unroll
        for (int i = 0; i < 8; i++) {
            int ch = tid + i * 128;
            int r = ch >> 4, c8 = (ch & 15) << 3;
            cp_async16(Vsh + r * 136 + c8,
                       &g_vh[(size_t)(k0 + r) * (HKV * DH) + kvh * DH + c8]);
        }
        asm volatile("cp.async.commit_group;");
    };

    float acc_o[16][4];
#pragma unroll
    for (int nt = 0; nt < 16; nt++)
#pragma unroll
        for (int i = 0; i < 4; i++) acc_o[nt][i] = 0.f;
    float l0 = 0.f, l1 = 0.f;
    int   mi0 = -10000, mi1 = -10000;

    const int ntiles = qi + 1;
    issueK(0);
    issueV(0);

    for (int t = 0; t < ntiles; t++) {
        const int k0 = t * 64;

        // ---- wait K(t) (pending {K(t),V(t)} -> wait 1 retires K(t))
        asm volatile("cp.async.wait_group 1;");
        __syncthreads();

        // ---- S2 = Q @ K^T  (fp16 mma)
        float acc_s[8][4];
#pragma unroll
        for (int nt = 0; nt < 8; nt++)
#pragma unroll
            for (int i = 0; i < 4; i++) acc_s[nt][i] = 0.f;
        const unsigned kb_base = ks_smem + h_lane_off;
#pragma unroll
        for (int kk = 0; kk < 8; kk++) {
#pragma unroll
            for (int ntp = 0; ntp < 4; ntp++) {
                unsigned kq[4];
                ldsm_x4(kq, kb_base + (unsigned)(ntp * 16 * 272) + kk * 32);
                unsigned b0[2] = { kq[0], kq[2] };
                unsigned b1[2] = { kq[1], kq[3] };
                mma_f16(acc_s[2 * ntp],     qf[kk], b0);
                mma_f16(acc_s[2 * ntp + 1], qf[kk], b1);
            }
        }
        __syncthreads();                 // K(t) consumed by all warps
        if (t + 1 < ntiles) issueK(t + 1);   // overlaps softmax + P@V

        // ---- causal mask (diag tile) + integer running max
        const bool diag = (t == ntiles - 1);
        const int r0 = q0 + wrow + g, r1 = r0 + 8;
        float mx0 = -1e30f, mx1 = -1e30f;
#pragma unroll
        for (int nt = 0; nt < 8; nt++) {
            if (diag) {
                int col0 = k0 + nt * 8 + tg * 2;
                if (col0     > r0) acc_s[nt][0] = -1e30f;
                if (col0 + 1 > r0) acc_s[nt][1] = -1e30f;
                if (col0     > r1) acc_s[nt][2] = -1e30f;
                if (col0 + 1 > r1) acc_s[nt][3] = -1e30f;
            }
            mx0 = fmaxf(mx0, fmaxf(acc_s[nt][0], acc_s[nt][1]));
            mx1 = fmaxf(mx1, fmaxf(acc_s[nt][2], acc_s[nt][3]));
        }
        mx0 = fmaxf(mx0, __shfl_xor_sync(0xffffffffu, mx0, 1));
        mx0 = fmaxf(mx0, __shfl_xor_sync(0xffffffffu, mx0, 2));
        mx1 = fmaxf(mx1, __shfl_xor_sync(0xffffffffu, mx1, 1));
        mx1 = fmaxf(mx1, __shfl_xor_sync(0xffffffffu, mx1, 2));
        int n0 = max(mi0, (int)ceilf(mx0));
        int n1 = max(mi1, (int)ceilf(mx1));
        float sc0 = pow2i(mi0 - n0);
        float sc1 = pow2i(mi1 - n1);
        mi0 = n0; mi1 = n1;
        l0 *= sc0; l1 *= sc1;
#pragma unroll
        for (int nt = 0; nt < 16; nt++) {
            acc_o[nt][0] *= sc0; acc_o[nt][1] *= sc0;
            acc_o[nt][2] *= sc1; acc_o[nt][3] *= sc1;
        }
        const float fm0 = (float)n0, fm1 = (float)n1;

        // ---- p = 2^(s - m) in (0,1]; 25% poly / 75% MUFU; store fp16
#pragma unroll
        for (int nt = 0; nt < 8; nt++) {
            float x0 = acc_s[nt][0] - fm0;
            float x1 = acc_s[nt][1] - fm0;
            float x2 = acc_s[nt][2] - fm1;
            float x3 = acc_s[nt][3] - fm1;
            float p0, p1, p2, p3;
            if (nt < 2) {
                p0 = exp2_poly(x0); p1 = exp2_poly(x1);
                p2 = exp2_poly(x2); p3 = exp2_poly(x3);
            } else {
                p0 = ex2_mufu(x0); p1 = ex2_mufu(x1);
                p2 = ex2_mufu(x2); p3 = ex2_mufu(x3);
            }
            l0 += p0 + p1;
            l1 += p2 + p3;
            *(__half2*)&Ps[(wrow + g) * 72 + nt * 8 + tg * 2]     = __floats2half2_rn(p0, p1);
            *(__half2*)&Ps[(wrow + g + 8) * 72 + nt * 8 + tg * 2] = __floats2half2_rn(p2, p3);
        }
        __syncwarp();   // Ps rows are warp-private

        // ---- wait V(t) (pending {V(t),K(t+1)} -> wait 1; last iter wait 0)
        if (t + 1 < ntiles) asm volatile("cp.async.wait_group 1;");
        else                asm volatile("cp.async.wait_group 0;");
        __syncthreads();   // V(t) visible to all warps

        // ---- O += P @ V  (fp16 mma; V b-frags via ldmatrix.trans)
#pragma unroll
        for (int kk = 0; kk < 4; kk++) {
            unsigned a[4];
            ldsm_x4(a, ps_base + kk * 32);
            const unsigned vkk = vs_smem + v_lane_off + (unsigned)(kk * 16 * 272);
#pragma unroll
            for (int np = 0; np < 8; np++) {
                unsigned kq[4];
                ldsm_x4_t(kq, vkk + np * 32);
                unsigned b0[2] = { kq[0], kq[1] };
                unsigned b1[2] = { kq[2], kq[3] };
                mma_f16(acc_o[np * 2],     a, b0);
                mma_f16(acc_o[np * 2 + 1], a, b1);
            }
        }
        __syncthreads();                 // V(t) consumed by all warps
        if (t + 1 < ntiles) issueV(t + 1);   // overlaps next S2 + softmax
    }

    l0 += __shfl_xor_sync(0xffffffffu, l0, 1);
    l0 += __shfl_xor_sync(0xffffffffu, l0, 2);
    l1 += __shfl_xor_sync(0xffffffffu, l1, 1);
    l1 += __shfl_xor_sync(0xffffffffu, l1, 2);
    const float inv0 = 1.f / l0;
    const float inv1 = 1.f / l1;

    const int row0 = q0 + wrow + g, row1 = row0 + 8;
#pragma unroll
    for (int nt = 0; nt < 16; nt++) {
        int col = h * DH + nt * 8 + tg * 2;
        *(__half2*)&g_attnh[(size_t)row0 * (HQ * DH) + col] =
            __floats2half2_rn(acc_o[nt][0] * inv0, acc_o[nt][1] * inv0);
        *(__half2*)&g_attnh[(size_t)row1 * (HQ * DH) + col] =
            __floats2half2_rn(acc_o[nt][2] * inv1, acc_o[nt][3] * inv1);
    }
}

// ---------------------------------------------------------------------------
// Launch pipeline (7 launches). Inputs:
// 0 H | 1 pos | 2 cos | 3 sin | 4 Wq | 5 Wk | 6 Wv | 7 Wo
// ---------------------------------------------------------------------------
extern "C" void kernel_launch(void* const* d_in, const int* in_sizes, int n_in,
                              void* d_out, int out_size)
{
    const float* H    = (const float*)d_in[0];
    const float* cosp = (const float*)d_in[2];
    const float* sinp = (const float*)d_in[3];
    const float* Wq   = (const float*)d_in[4];
    const float* Wk   = (const float*)d_in[5];
    const float* Wv   = (const float*)d_in[6];
    const float* Wo   = (const float*)d_in[7];
    float* out = (float*)d_out;

    float *qkv;
    __half *attnh, *Hh, *Wh, *Woh;
    cudaGetSymbolAddress((void**)&qkv,   g_qkv);
    cudaGetSymbolAddress((void**)&attnh, g_attnh);
    cudaGetSymbolAddress((void**)&Hh,    g_Hh);
    cudaGetSymbolAddress((void**)&Wh,    g_Wh);
    cudaGetSymbolAddress((void**)&Woh,   g_Woh);

    cudaFuncSetAttribute(h16gemm, cudaFuncAttributeMaxDynamicSharedMemorySize, GEMMH_SMEM);
    cudaFuncSetAttribute(attn_mma_kernel, cudaFuncAttributeMaxDynamicSharedMemorySize, ATT_SMEM_BYTES);

    // Prep (3 launches)
    prep_H_half<<<512, 256>>>((const float4*)H, (__half2*)Hh);
    prep_transpose_QO<<<dim3(128, 128, 2), dim3(32, 8)>>>(Wq, Wo, Wh, Woh);
    prep_transpose_KV<<<dim3(32, 128, 2), dim3(32, 8)>>>(Wk, Wv, Wh);

    // Fused QKV projection, fp16 tensor cores (launch 4)
    h16gemm<<<dim3(QKV_N / 128, T_SEQ / 128), 256, GEMMH_SMEM>>>(
        Hh, Wh, qkv, T_SEQ, QKV_N, HID);

    // RoPE -> fp16 Q/K/V (launch 5)
    rope_split_kernel<<<T_SEQ, 256>>>(cosp, sinp);

    // Attention: all-fp16 MMA, cp.async pipelined, 3 CTAs/SM (launch 6)
    attn_mma_kernel<<<dim3(T_SEQ / 64, HQ), 128, ATT_SMEM_BYTES>>>();

    // Output projection, fp16 tensor cores (launch 7)
    h16gemm<<<dim3(HID / 128, T_SEQ / 128), 256, GEMMH_SMEM>>>(
        attnh, Woh, out, T_SEQ, HID, HQ * DH);
}

// round 17
// speedup vs baseline: 2.6237x; 1.0269x over previous
#include <cuda_runtime.h>
#include <cuda_bf16.h>
#include <cuda_fp16.h>
#include <math.h>

#define T_SEQ 2048
#define HID   4096
#define HQ    32
#define HKV   8
#define DH    128
#define GROUPS (HQ / HKV)
#define QKV_N 6144                      // 4096 q | 1024 k | 1024 v
#define K_OFF 4096
#define V_OFF 5120

// q pre-scale: 1/sqrt(128) * log2(e)  (softmax runs in exp2 domain)
#define QSCALE_F ((float)(0.08838834764831845 * 1.4426950408889634))

// ---------------- device scratch (no allocs allowed) ----------------
__device__ float  g_qkv[T_SEQ * QKV_N];       // 50 MB  fused q|k (fp32, GEMM out; V region unused)
__device__ __half g_qh [T_SEQ * HQ * DH];     // 16 MB  roped+scaled Q (fp16)
__device__ __half g_kh [T_SEQ * HKV * DH];    // 4 MB   roped K (fp16)
__device__ __half g_vh [T_SEQ * HKV * DH];    // 4 MB   V (fp16, written by GEMM epilogue)
__device__ __half g_attnh[T_SEQ * HQ * DH];   // 16 MB  attention out (fp16)
__device__ __half g_Hh [T_SEQ * HID];         // 16 MB  fp16 H [M][K]
__device__ __half g_Wh [QKV_N * HID];         // 48 MB  fp16 [Wq|Wk|Wv] transposed [N][K]
__device__ __half g_Woh[HID * HQ * DH];       // 32 MB  fp16 Wo transposed [N][K]

__device__ __forceinline__ void mma_f16(float* d, const unsigned* a, const unsigned* b) {
    asm volatile(
        "mma.sync.aligned.m16n8k16.row.col.f32.f16.f16.f32 "
        "{%0,%1,%2,%3}, {%4,%5,%6,%7}, {%8,%9}, {%0,%1,%2,%3};"
        : "+f"(d[0]), "+f"(d[1]), "+f"(d[2]), "+f"(d[3])
        : "r"(a[0]), "r"(a[1]), "r"(a[2]), "r"(a[3]), "r"(b[0]), "r"(b[1]));
}

// ldmatrix x4: lane L supplies the 16B row address of matrix (L>>3).
__device__ __forceinline__ void ldsm_x4(unsigned* r, unsigned a) {
    asm volatile("ldmatrix.sync.aligned.m8n8.x4.shared.b16 {%0,%1,%2,%3}, [%4];"
                 : "=r"(r[0]), "=r"(r[1]), "=r"(r[2]), "=r"(r[3]) : "r"(a));
}
// transposed variant (k-major B tiles) -> fp16 mma b-frag distribution.
__device__ __forceinline__ void ldsm_x4_t(unsigned* r, unsigned a) {
    asm volatile("ldmatrix.sync.aligned.m8n8.x4.trans.shared.b16 {%0,%1,%2,%3}, [%4];"
                 : "=r"(r[0]), "=r"(r[1]), "=r"(r[2]), "=r"(r[3]) : "r"(a));
}

__device__ __forceinline__ void cp_async16(void* smem_dst, const void* gmem_src) {
    unsigned s = (unsigned)__cvta_generic_to_shared(smem_dst);
    asm volatile("cp.async.cg.shared.global [%0], [%1], 16;" :: "r"(s), "l"(gmem_src));
}

// MUFU exp2
__device__ __forceinline__ float ex2_mufu(float x) {
    float y;
    asm("ex2.approx.ftz.f32 %0, %1;" : "=f"(y) : "f"(x));
    return y;
}

// FMA-pipe exp2: minimax on f in [-0.5, 0.5], ~1e-7 rel err.
__device__ __forceinline__ float exp2_poly(float x) {
    x = fmaxf(x, -120.f);
    float t = x + 12582912.f;
    float i = t - 12582912.f;
    float f = x - i;
    float p = 1.535336188319500e-4f;
    p = fmaf(p, f, 1.339887440266574e-3f);
    p = fmaf(p, f, 9.618437357674640e-3f);
    p = fmaf(p, f, 5.550332471162809e-2f);
    p = fmaf(p, f, 2.402264791363012e-1f);
    p = fmaf(p, f, 6.931472028550421e-1f);
    p = fmaf(p, f, 1.0f);
    int ii = (int)i;
    return p * __int_as_float((ii + 127) << 23);
}

// exact 2^d for integer d <= 0 (0 if underflow)
__device__ __forceinline__ float pow2i(int d) {
    int b = 127 + d;
    return (b > 0) ? __int_as_float(b << 23) : 0.f;
}

// ---------------------------------------------------------------------------
// Prep 1: convert H to fp16 [M][K]
// ---------------------------------------------------------------------------
__global__ void prep_H_half(const float4* __restrict__ H, __half2* __restrict__ Hh)
{
    const int n4 = T_SEQ * HID / 4;
    int stride = gridDim.x * blockDim.x;
    for (int i = blockIdx.x * blockDim.x + threadIdx.x; i < n4; i += stride) {
        float4 v = H[i];
        Hh[i * 2]     = __floats2half2_rn(v.x, v.y);
        Hh[i * 2 + 1] = __floats2half2_rn(v.z, v.w);
    }
}

// ---------------------------------------------------------------------------
// Prep 2: transpose+convert Wq and Wo (4096x4096) -> fp16 [N][K] via blockIdx.z
// ---------------------------------------------------------------------------
__global__ void prep_transpose_QO(const float* __restrict__ Wq,
                                  const float* __restrict__ Wo,
                                  __half* __restrict__ Wh,
                                  __half* __restrict__ Woh)
{
    __shared__ float tile[32][33];
    const float* W = blockIdx.z ? Wo : Wq;
    __half* dst    = blockIdx.z ? Woh : Wh;
    const int N = 4096, K = 4096;
    int x = blockIdx.x * 32 + threadIdx.x;
#pragma unroll
    for (int j = 0; j < 4; j++) {
        int y = blockIdx.y * 32 + threadIdx.y + j * 8;
        tile[threadIdx.y + j * 8][threadIdx.x] = W[(size_t)y * N + x];
    }
    __syncthreads();
    int k = blockIdx.y * 32 + threadIdx.x;
#pragma unroll
    for (int j = 0; j < 4; j++) {
        int n = blockIdx.x * 32 + threadIdx.y + j * 8;
        dst[(size_t)n * K + k] = __float2half_rn(tile[threadIdx.x][threadIdx.y + j * 8]);
    }
}

// ---------------------------------------------------------------------------
// Prep 3: transpose+convert Wk (rows 4096..) / Wv (rows 5120..) via blockIdx.z
// ---------------------------------------------------------------------------
__global__ void prep_transpose_KV(const float* __restrict__ Wk,
                                  const float* __restrict__ Wv,
                                  __half* __restrict__ Wh)
{
    __shared__ float tile[32][33];
    const float* W = blockIdx.z ? Wv : Wk;
    const int rowOff = blockIdx.z ? V_OFF : K_OFF;
    const int N = 1024, K = 4096;
    int x = blockIdx.x * 32 + threadIdx.x;
#pragma unroll
    for (int j = 0; j < 4; j++) {
        int y = blockIdx.y * 32 + threadIdx.y + j * 8;
        tile[threadIdx.y + j * 8][threadIdx.x] = W[(size_t)y * N + x];
    }
    __syncthreads();
    int k = blockIdx.y * 32 + threadIdx.x;
#pragma unroll
    for (int j = 0; j < 4; j++) {
        int n = blockIdx.x * 32 + threadIdx.y + j * 8;
        Wh[(size_t)(rowOff + n) * K + k] = __float2half_rn(tile[threadIdx.x][threadIdx.y + j * 8]);
    }
}

// ---------------------------------------------------------------------------
// FP16 tensor GEMM: C[M,N] = A[M,K] @ Bt[N,K]^T, fp32 accumulate.
// CTA tile 128x128x64, 256 threads, 2 CTAs/SM, 3-stage cp.async, ldmatrix both.
// NEW: fragment double-buffering across kk (LDSM latency hidden behind MMAs).
// vmode: if nonzero and bn >= V_OFF, epilogue writes fp16 g_vh instead of fp32 C.
// ---------------------------------------------------------------------------
#define GEMMH_SMEM (3 * 2 * 128 * 72 * 2)

__global__ __launch_bounds__(256, 2) void h16gemm(const __half* __restrict__ A,
                                                  const __half* __restrict__ Bt,
                                                  float* __restrict__ C,
                                                  int M, int N, int K, int vmode)
{
    extern __shared__ __half smh[];
    const int tid  = threadIdx.x;
    const int wid  = tid >> 5;
    const int lane = tid & 31;
    const int g    = lane >> 2;
    const int tg   = lane & 3;
    const int wm   = (wid >> 2) * 64;
    const int wn   = (wid & 3) * 32;
    const int bm   = blockIdx.y * 128;
    const int bn   = blockIdx.x * 128;

    const __half* Ab = A  + (size_t)bm * K;
    const __half* Bb = Bt + (size_t)bn * K;

    const unsigned lane_off = ((lane & 15) * 144) + ((lane >> 4) * 16);

    float acc[4][4][4];
#pragma unroll
    for (int mt = 0; mt < 4; mt++)
#pragma unroll
        for (int nt = 0; nt < 4; nt++)
#pragma unroll
            for (int i = 0; i < 4; i++) acc[mt][nt][i] = 0.f;

    const int ntiles = K >> 6;

    auto issue = [&](int t) {
        __half* As_ = smh + (t % 3) * 18432;
        __half* Bs_ = As_ + 9216;
        const int kt = t << 6;
#pragma unroll
        for (int i_ = 0; i_ < 4; i_++) {
            int ch = tid + i_ * 256;
            int r = ch >> 3, c = ch & 7;
            cp_async16(As_ + r * 72 + c * 8, Ab + (size_t)r * K + kt + c * 8);
            cp_async16(Bs_ + r * 72 + c * 8, Bb + (size_t)r * K + kt + c * 8);
        }
        asm volatile("cp.async.commit_group;");
    };

    issue(0);
    issue(1);

    unsigned af[2][4][4], bq[2][2][4];

    for (int t = 0; t < ntiles; t++) {
        if (t == ntiles - 1) asm volatile("cp.async.wait_group 0;");
        else                 asm volatile("cp.async.wait_group 1;");
        __syncthreads();
        if (t + 2 < ntiles) issue(t + 2);

        const __half* As_ = smh + (t % 3) * 18432;
        const __half* Bs_ = As_ + 9216;
        const unsigned a_base = (unsigned)__cvta_generic_to_shared(As_) + lane_off;
        const unsigned b_base = (unsigned)__cvta_generic_to_shared(Bs_) + lane_off;

        // prime fragment buffer 0 (kk = 0)
#pragma unroll
        for (int mt = 0; mt < 4; mt++)
            ldsm_x4(af[0][mt], a_base + (wm + mt * 16) * 144);
#pragma unroll
        for (int np = 0; np < 2; np++)
            ldsm_x4(bq[0][np], b_base + (wn + np * 16) * 144);

#pragma unroll
        for (int kki = 0; kki < 4; kki++) {
            const int cur = kki & 1, nxt = cur ^ 1;
            if (kki < 3) {                 // prefetch kk+1 frags before MMAs
                const int kk2 = (kki + 1) * 32;   // fp16 elems *2 bytes = *32
#pragma unroll
                for (int mt = 0; mt < 4; mt++)
                    ldsm_x4(af[nxt][mt], a_base + (wm + mt * 16) * 144 + kk2);
#pragma unroll
                for (int np = 0; np < 2; np++)
                    ldsm_x4(bq[nxt][np], b_base + (wn + np * 16) * 144 + kk2);
            }
#pragma unroll
            for (int mt = 0; mt < 4; mt++)
#pragma unroll
                for (int nt = 0; nt < 4; nt++) {
                    unsigned b[2] = { bq[cur][nt >> 1][nt & 1],
                                      bq[cur][nt >> 1][(nt & 1) + 2] };
                    mma_f16(acc[mt][nt], af[cur][mt], b);
                }
        }
    }

    if (vmode && bn >= V_OFF) {
        // V region: write fp16 g_vh[t][vcol] directly (row = seq pos)
        const int vbn = bn - V_OFF;
#pragma unroll
        for (int mt = 0; mt < 4; mt++) {
#pragma unroll
            for (int nt = 0; nt < 4; nt++) {
                int row = bm + wm + mt * 16 + g;
                int col = vbn + wn + nt * 8 + tg * 2;
                *(__half2*)&g_vh[(size_t)row * (HKV * DH) + col] =
                    __floats2half2_rn(acc[mt][nt][0], acc[mt][nt][1]);
                *(__half2*)&g_vh[(size_t)(row + 8) * (HKV * DH) + col] =
                    __floats2half2_rn(acc[mt][nt][2], acc[mt][nt][3]);
            }
        }
    } else {
#pragma unroll
        for (int mt = 0; mt < 4; mt++) {
#pragma unroll
            for (int nt = 0; nt < 4; nt++) {
                int row = bm + wm + mt * 16 + g;
                int col = bn + wn + nt * 8 + tg * 2;
                *(float2*)&C[(size_t)row * N + col]       = make_float2(acc[mt][nt][0], acc[mt][nt][1]);
                *(float2*)&C[(size_t)(row + 8) * N + col] = make_float2(acc[mt][nt][2], acc[mt][nt][3]);
            }
        }
    }
}

// ---------------------------------------------------------------------------
// RoPE: reads fused qkv (fp32, Q/K regions only); writes Q (scaled) / K fp16.
// (V handled by the QKV GEMM epilogue.)
// ---------------------------------------------------------------------------
__global__ void rope_split_kernel(const float* __restrict__ cosp,
                                  const float* __restrict__ sinp)
{
    const int t = blockIdx.x;
    const float* rowp = &g_qkv[(size_t)t * QKV_N];
    for (int p = threadIdx.x; p < (HQ + HKV) * 64; p += blockDim.x) {
        int h = p >> 6;
        int d = p & 63;
        float c = cosp[t * DH + d];
        float s = sinp[t * DH + d];
        if (h < HQ) {
            const float* base = rowp + h * DH;
            float x1 = base[d], x2 = base[d + 64];
            __half* qb = &g_qh[(size_t)t * (HQ * DH) + h * DH];
            qb[d]      = __float2half_rn((x1 * c - x2 * s) * QSCALE_F);
            qb[d + 64] = __float2half_rn((x2 * c + x1 * s) * QSCALE_F);
        } else {
            const float* base = rowp + K_OFF + (h - HQ) * DH;
            float x1 = base[d], x2 = base[d + 64];
            __half* kb = &g_kh[(size_t)t * (HKV * DH) + (h - HQ) * DH];
            kb[d]      = __float2half_rn(x1 * c - x2 * s);
            kb[d + 64] = __float2half_rn(x2 * c + x1 * s);
        }
    }
}

// ---------------------------------------------------------------------------
// Flash attention (R16 exact), all-fp16 MMA + cp.async-pipelined K/V loads.
// 64 queries x 1 head, 128 threads, 3 CTAs/SM. smem 44,032 B.
// ---------------------------------------------------------------------------
#define ATT_SMEM_BYTES (17408 + 17408 + 9216)

__global__ __launch_bounds__(128, 3) void attn_mma_kernel()
{
    extern __shared__ char smb[];
    __half* Ksh = (__half*)smb;                  // [64][136]
    __half* Vsh = (__half*)(smb + 17408);        // [64][136]
    __half* Ps  = (__half*)(smb + 34816);        // [64][72]

    const int h    = blockIdx.y;
    const int kvh  = h / GROUPS;
    const int qi   = gridDim.x - 1 - blockIdx.x;   // long CTAs first
    const int q0   = qi * 64;
    const int tid  = threadIdx.x;
    const int w    = tid >> 5;
    const int lane = tid & 31;
    const int g    = lane >> 2;
    const int tg   = lane & 3;
    const int wrow = w * 16;

    const unsigned h_lane_off = ((lane & 15) * 272) + ((lane >> 4) * 16);
    const unsigned p_lane_off = ((lane & 15) * 144) + ((lane >> 4) * 16);
    const unsigned v_lane_off = ((((lane >> 3) & 1) * 8 + (lane & 7)) * 272)
                                + (((lane >> 3) >> 1) * 16);
    const unsigned ks_smem = (unsigned)__cvta_generic_to_shared(Ksh);
    const unsigned vs_smem = (unsigned)__cvta_generic_to_shared(Vsh);
    const unsigned ps_base = (unsigned)__cvta_generic_to_shared(Ps) + p_lane_off
                             + (unsigned)(wrow * 144);

    for (int idx = tid; idx < 64 * 16; idx += 128) {
        int r = idx >> 4, c8 = (idx & 15) << 3;
        *(float4*)&Ksh[r * 136 + c8] =
            *(const float4*)&g_qh[(size_t)(q0 + r) * (HQ * DH) + h * DH + c8];
    }
    __syncthreads();
    unsigned qf[8][4];
    {
        const unsigned q_base = ks_smem + h_lane_off + (unsigned)(wrow * 272);
#pragma unroll
        for (int kk = 0; kk < 8; kk++)
            ldsm_x4(qf[kk], q_base + kk * 32);
    }
    __syncthreads();   // Q frags read before K(0) cp.async overwrites Ksh

    auto issueK = [&](int t) {
        const int k0 = t * 64;
#pragma unroll
        for (int i = 0; i < 8; i++) {
            int ch = tid + i * 128;
            int r = ch >> 4, c8 = (ch & 15) << 3;
            cp_async16(Ksh + r * 136 + c8,
                       &g_kh[(size_t)(k0 + r) * (HKV * DH) + kvh * DH + c8]);
        }
        asm volatile("cp.async.commit_group;");
    };
    auto issueV = [&](int t) {
        const int k0 = t * 64;
#pragma unroll
        for (int i = 0; i < 8; i++) {
            int ch = tid + i * 128;
            int r = ch >> 4, c8 = (ch & 15) << 3;
            cp_async16(Vsh + r * 136 + c8,
                       &g_vh[(size_t)(k0 + r) * (HKV * DH) + kvh * DH + c8]);
        }
        asm volatile("cp.async.commit_group;");
    };

    float acc_o[16][4];
#pragma unroll
    for (int nt = 0; nt < 16; nt++)
#pragma unroll
        for (int i = 0; i < 4; i++) acc_o[nt][i] = 0.f;
    float l0 = 0.f, l1 = 0.f;
    int   mi0 = -10000, mi1 = -10000;

    const int ntiles = qi + 1;
    issueK(0);
    issueV(0);

    for (int t = 0; t < ntiles; t++) {
        const int k0 = t * 64;

        asm volatile("cp.async.wait_group 1;");
        __syncthreads();

        float acc_s[8][4];
#pragma unroll
        for (int nt = 0; nt < 8; nt++)
#pragma unroll
            for (int i = 0; i < 4; i++) acc_s[nt][i] = 0.f;
        const unsigned kb_base = ks_smem + h_lane_off;
#pragma unroll
        for (int kk = 0; kk < 8; kk++) {
#pragma unroll
            for (int ntp = 0; ntp < 4; ntp++) {
                unsigned kq[4];
                ldsm_x4(kq, kb_base + (unsigned)(ntp * 16 * 272) + kk * 32);
                unsigned b0[2] = { kq[0], kq[2] };
                unsigned b1[2] = { kq[1], kq[3] };
                mma_f16(acc_s[2 * ntp],     qf[kk], b0);
                mma_f16(acc_s[2 * ntp + 1], qf[kk], b1);
            }
        }
        __syncthreads();
        if (t + 1 < ntiles) issueK(t + 1);

        const bool diag = (t == ntiles - 1);
        const int r0 = q0 + wrow + g, r1 = r0 + 8;
        float mx0 = -1e30f, mx1 = -1e30f;
#pragma unroll
        for (int nt = 0; nt < 8; nt++) {
            if (diag) {
                int col0 = k0 + nt * 8 + tg * 2;
                if (col0     > r0) acc_s[nt][0] = -1e30f;
                if (col0 + 1 > r0) acc_s[nt][1] = -1e30f;
                if (col0     > r1) acc_s[nt][2] = -1e30f;
                if (col0 + 1 > r1) acc_s[nt][3] = -1e30f;
            }
            mx0 = fmaxf(mx0, fmaxf(acc_s[nt][0], acc_s[nt][1]));
            mx1 = fmaxf(mx1, fmaxf(acc_s[nt][2], acc_s[nt][3]));
        }
        mx0 = fmaxf(mx0, __shfl_xor_sync(0xffffffffu, mx0, 1));
        mx0 = fmaxf(mx0, __shfl_xor_sync(0xffffffffu, mx0, 2));
        mx1 = fmaxf(mx1, __shfl_xor_sync(0xffffffffu, mx1, 1));
        mx1 = fmaxf(mx1, __shfl_xor_sync(0xffffffffu, mx1, 2));
        int n0 = max(mi0, (int)ceilf(mx0));
        int n1 = max(mi1, (int)ceilf(mx1));
        float sc0 = pow2i(mi0 - n0);
        float sc1 = pow2i(mi1 - n1);
        mi0 = n0; mi1 = n1;
        l0 *= sc0; l1 *= sc1;
#pragma unroll
        for (int nt = 0; nt < 16; nt++) {
            acc_o[nt][0] *= sc0; acc_o[nt][1] *= sc0;
            acc_o[nt][2] *= sc1; acc_o[nt][3] *= sc1;
        }
        const float fm0 = (float)n0, fm1 = (float)n1;

#pragma unroll
        for (int nt = 0; nt < 8; nt++) {
            float x0 = acc_s[nt][0] - fm0;
            float x1 = acc_s[nt][1] - fm0;
            float x2 = acc_s[nt][2] - fm1;
            float x3 = acc_s[nt][3] - fm1;
            float p0, p1, p2, p3;
            if (nt < 2) {
                p0 = exp2_poly(x0); p1 = exp2_poly(x1);
                p2 = exp2_poly(x2); p3 = exp2_poly(x3);
            } else {
                p0 = ex2_mufu(x0); p1 = ex2_mufu(x1);
                p2 = ex2_mufu(x2); p3 = ex2_mufu(x3);
            }
            l0 += p0 + p1;
            l1 += p2 + p3;
            *(__half2*)&Ps[(wrow + g) * 72 + nt * 8 + tg * 2]     = __floats2half2_rn(p0, p1);
            *(__half2*)&Ps[(wrow + g + 8) * 72 + nt * 8 + tg * 2] = __floats2half2_rn(p2, p3);
        }
        __syncwarp();

        if (t + 1 < ntiles) asm volatile("cp.async.wait_group 1;");
        else                asm volatile("cp.async.wait_group 0;");
        __syncthreads();

#pragma unroll
        for (int kk = 0; kk < 4; kk++) {
            unsigned a[4];
            ldsm_x4(a, ps_base + kk * 32);
            const unsigned vkk = vs_smem + v_lane_off + (unsigned)(kk * 16 * 272);
#pragma unroll
            for (int np = 0; np < 8; np++) {
                unsigned kq[4];
                ldsm_x4_t(kq, vkk + np * 32);
                unsigned b0[2] = { kq[0], kq[1] };
                unsigned b1[2] = { kq[2], kq[3] };
                mma_f16(acc_o[np * 2],     a, b0);
                mma_f16(acc_o[np * 2 + 1], a, b1);
            }
        }
        __syncthreads();
        if (t + 1 < ntiles) issueV(t + 1);
    }

    l0 += __shfl_xor_sync(0xffffffffu, l0, 1);
    l0 += __shfl_xor_sync(0xffffffffu, l0, 2);
    l1 += __shfl_xor_sync(0xffffffffu, l1, 1);
    l1 += __shfl_xor_sync(0xffffffffu, l1, 2);
    const float inv0 = 1.f / l0;
    const float inv1 = 1.f / l1;

    const int row0 = q0 + wrow + g, row1 = row0 + 8;
#pragma unroll
    for (int nt = 0; nt < 16; nt++) {
        int col = h * DH + nt * 8 + tg * 2;
        *(__half2*)&g_attnh[(size_t)row0 * (HQ * DH) + col] =
            __floats2half2_rn(acc_o[nt][0] * inv0, acc_o[nt][1] * inv0);
        *(__half2*)&g_attnh[(size_t)row1 * (HQ * DH) + col] =
            __floats2half2_rn(acc_o[nt][2] * inv1, acc_o[nt][3] * inv1);
    }
}

// ---------------------------------------------------------------------------
// Launch pipeline (7 launches). Inputs:
// 0 H | 1 pos | 2 cos | 3 sin | 4 Wq | 5 Wk | 6 Wv | 7 Wo
// ---------------------------------------------------------------------------
extern "C" void kernel_launch(void* const* d_in, const int* in_sizes, int n_in,
                              void* d_out, int out_size)
{
    const float* H    = (const float*)d_in[0];
    const float* cosp = (const float*)d_in[2];
    const float* sinp = (const float*)d_in[3];
    const float* Wq   = (const float*)d_in[4];
    const float* Wk   = (const float*)d_in[5];
    const float* Wv   = (const float*)d_in[6];
    const float* Wo   = (const float*)d_in[7];
    float* out = (float*)d_out;

    float *qkv;
    __half *attnh, *Hh, *Wh, *Woh;
    cudaGetSymbolAddress((void**)&qkv,   g_qkv);
    cudaGetSymbolAddress((void**)&attnh, g_attnh);
    cudaGetSymbolAddress((void**)&Hh,    g_Hh);
    cudaGetSymbolAddress((void**)&Wh,    g_Wh);
    cudaGetSymbolAddress((void**)&Woh,   g_Woh);

    cudaFuncSetAttribute(h16gemm, cudaFuncAttributeMaxDynamicSharedMemorySize, GEMMH_SMEM);
    cudaFuncSetAttribute(attn_mma_kernel, cudaFuncAttributeMaxDynamicSharedMemorySize, ATT_SMEM_BYTES);

    // Prep (3 launches)
    prep_H_half<<<512, 256>>>((const float4*)H, (__half2*)Hh);
    prep_transpose_QO<<<dim3(128, 128, 2), dim3(32, 8)>>>(Wq, Wo, Wh, Woh);
    prep_transpose_KV<<<dim3(32, 128, 2), dim3(32, 8)>>>(Wk, Wv, Wh);

    // Fused QKV projection (launch 4); V columns -> fp16 g_vh in epilogue
    h16gemm<<<dim3(QKV_N / 128, T_SEQ / 128), 256, GEMMH_SMEM>>>(
        Hh, Wh, qkv, T_SEQ, QKV_N, HID, 1);

    // RoPE -> fp16 Q/K (launch 5)
    rope_split_kernel<<<T_SEQ, 256>>>(cosp, sinp);

    // Attention: all-fp16 MMA, cp.async pipelined, 3 CTAs/SM (launch 6)
    attn_mma_kernel<<<dim3(T_SEQ / 64, HQ), 128, ATT_SMEM_BYTES>>>();

    // Output projection (launch 7)
    h16gemm<<<dim3(HID / 128, T_SEQ / 128), 256, GEMMH_SMEM>>>(
        attnh, Woh, out, T_SEQ, HID, HQ * DH, 0);
}